// round 11
// baseline (speedup 1.0000x reference)
#include <cuda_runtime.h>
#include <cuda_fp16.h>
#include <math.h>
#include <stdint.h>

// ---------------------------------------------------------------------------
// Problem constants
// ---------------------------------------------------------------------------
#define BATCH 4
#define SEQ   2048
#define DMODEL 1024
#define NHEAD 16
#define HDIM  64
#define ROWS  (BATCH * SEQ)          // 8192
#define EPS   1e-5f

// ---------------------------------------------------------------------------
// Scratch buffers (static device globals: allocation-free per harness rules)
// ---------------------------------------------------------------------------
__device__ __half g_lnh[ROWS * DMODEL];       // 16 MB  LN output (fp16, GEMM A)
__device__ float  g_qkv[ROWS * 3 * DMODEL];   // 96 MB  qkv (fp32, attention in)
__device__ __half g_yh [ROWS * DMODEL];       // 16 MB  attention out (fp16)
__device__ float  g_x1 [ROWS * DMODEL];       // 32 MB  residual after attn
__device__ __half g_hh [ROWS * 4 * DMODEL];   // 64 MB  MLP hidden (fp16)
// fp16, TRANSPOSED weights [N][K]
__device__ __half g_wa [3 * DMODEL * DMODEL]; // 6 MB
__device__ __half g_wo [DMODEL * DMODEL];     // 2 MB
__device__ __half g_wf [4 * DMODEL * DMODEL]; // 8 MB
__device__ __half g_wp [DMODEL * 4 * DMODEL]; // 8 MB

// ---------------------------------------------------------------------------
// Helpers
// ---------------------------------------------------------------------------
__device__ __forceinline__ uint32_t smem_u32(const void* p) {
    uint32_t a;
    asm("{ .reg .u64 t; cvta.to.shared.u64 t, %1; cvt.u32.u64 %0, t; }"
        : "=r"(a) : "l"(p));
    return a;
}

#define SMEM_SWIZZLE_128B(off) ((off) ^ (((off) >> 3) & 0x70))

__device__ __forceinline__ unsigned f2tf32(float f) {
    unsigned r;
    asm("cvt.rna.tf32.f32 %0, %1;" : "=r"(r) : "f"(f));
    return r;
}
__device__ __forceinline__ float roundtf32(float f) {
    return __uint_as_float(f2tf32(f));
}

__device__ __forceinline__ void ldsm4(unsigned& r0, unsigned& r1,
                                      unsigned& r2, unsigned& r3, uint32_t a) {
    asm volatile("ldmatrix.sync.aligned.m8n8.x4.shared.b16 {%0,%1,%2,%3}, [%4];"
                 : "=r"(r0), "=r"(r1), "=r"(r2), "=r"(r3) : "r"(a));
}

__device__ __forceinline__ void mma_f16(float* c,
                                        unsigned a0, unsigned a1,
                                        unsigned a2, unsigned a3,
                                        unsigned b0, unsigned b1) {
    asm volatile(
        "mma.sync.aligned.m16n8k16.row.col.f32.f16.f16.f32 "
        "{%0,%1,%2,%3}, {%4,%5,%6,%7}, {%8,%9}, {%0,%1,%2,%3};"
        : "+f"(c[0]), "+f"(c[1]), "+f"(c[2]), "+f"(c[3])
        : "r"(a0), "r"(a1), "r"(a2), "r"(a3), "r"(b0), "r"(b1));
}

__device__ __forceinline__ void mma_tf32(float* c,
                                         unsigned a0, unsigned a1,
                                         unsigned a2, unsigned a3,
                                         unsigned b0, unsigned b1) {
    asm volatile(
        "mma.sync.aligned.m16n8k8.row.col.f32.tf32.tf32.f32 "
        "{%0,%1,%2,%3}, {%4,%5,%6,%7}, {%8,%9}, {%0,%1,%2,%3};"
        : "+f"(c[0]), "+f"(c[1]), "+f"(c[2]), "+f"(c[3])
        : "r"(a0), "r"(a1), "r"(a2), "r"(a3), "r"(b0), "r"(b1));
}

__device__ __forceinline__ float gelu_tanh(float x) {
    const float c0 = 0.7978845608028654f;  // sqrt(2/pi)
    const float c1 = 0.044715f;
    float t = tanhf(c0 * (x + c1 * x * x * x));
    return 0.5f * x * (1.0f + t);
}

// Transpose + fp16-convert a weight matrix: in [K][N] fp32 -> out [N][K] fp16
__global__ __launch_bounds__(256) void transpose_h_kernel(
    const float* __restrict__ in, __half* __restrict__ out, int K, int N)
{
    __shared__ float t[32][33];
    const int n0 = blockIdx.x * 32;
    const int k0 = blockIdx.y * 32;
    const int tx = threadIdx.x, ty = threadIdx.y;
#pragma unroll
    for (int i = 0; i < 4; i++)
        t[ty + 8 * i][tx] = in[(size_t)(k0 + ty + 8 * i) * N + n0 + tx];
    __syncthreads();
#pragma unroll
    for (int i = 0; i < 4; i++)
        out[(size_t)(n0 + ty + 8 * i) * K + k0 + tx] =
            __float2half_rn(t[tx][ty + 8 * i]);
}

// ---------------------------------------------------------------------------
// LayerNorm: fp32 in, fp16 out
// ---------------------------------------------------------------------------
__device__ __forceinline__ float warp_sum(float v) {
#pragma unroll
    for (int o = 16; o > 0; o >>= 1) v += __shfl_xor_sync(0xffffffffu, v, o);
    return v;
}

__global__ __launch_bounds__(256) void ln_kernel(
    const float* __restrict__ x,
    const float* __restrict__ g,
    const float* __restrict__ b,
    __half* __restrict__ out)
{
    const int row = blockIdx.x;
    const int tid = threadIdx.x;
    const float4 v = reinterpret_cast<const float4*>(x + (size_t)row * DMODEL)[tid];

    float s  = v.x + v.y + v.z + v.w;
    float ss = v.x*v.x + v.y*v.y + v.z*v.z + v.w*v.w;
    s  = warp_sum(s);
    ss = warp_sum(ss);

    __shared__ float red0[8], red1[8];
    const int wid = tid >> 5, lane = tid & 31;
    if (lane == 0) { red0[wid] = s; red1[wid] = ss; }
    __syncthreads();
    float ts = 0.f, tss = 0.f;
#pragma unroll
    for (int w = 0; w < 8; w++) { ts += red0[w]; tss += red1[w]; }

    const float mean = ts * (1.0f / DMODEL);
    const float var  = tss * (1.0f / DMODEL) - mean * mean;
    const float rstd = rsqrtf(var + EPS);

    const float4 gv = reinterpret_cast<const float4*>(g)[tid];
    const float4 bv = reinterpret_cast<const float4*>(b)[tid];
    __half2 h0 = __floats2half2_rn((v.x - mean) * rstd * gv.x + bv.x,
                                   (v.y - mean) * rstd * gv.y + bv.y);
    __half2 h1 = __floats2half2_rn((v.z - mean) * rstd * gv.z + bv.z,
                                   (v.w - mean) * rstd * gv.w + bv.w);
    __half2* op = reinterpret_cast<__half2*>(out + (size_t)row * DMODEL);
    op[tid * 2 + 0] = h0;
    op[tid * 2 + 1] = h1;
}

// ---------------------------------------------------------------------------
// FP16 tensor-core GEMM v2: C[M,N] = A[M,K] @ W[K,N], W transposed fp16
// Bt[N][K].  CTA tile 128x256, BK=64 (128B/row SW128), 256 threads
// (8 warps as 2x4 -> 64x64 warp tiles), mma.m16n8k16.f16,
// 4-stage cp.async pipeline (192 KB smem, 1 CTA/SM).
// Per ks-step: 8 ldsm4 -> 32 HMMA (0.25 loads per mma).
// EPI: 0 none(f32) | 1 +res(f32) | 2 gelu(acc+bias)->fp16 | 3 +bias+res(f32)
// ---------------------------------------------------------------------------
#define HG_NSTG   4
#define HG_ATILE  16384                      // 128 rows x 128 bytes
#define HG_BTILE  32768                      // 256 rows x 128 bytes
#define HG_STAGE  (HG_ATILE + HG_BTILE)      // 49152
#define HG_A_OFF(s) ((s) * HG_STAGE)
#define HG_B_OFF(s) ((s) * HG_STAGE + HG_ATILE)
#define HG_SMEM   (HG_NSTG * HG_STAGE)       // 196608 B

__device__ __forceinline__ void hg_load_chunk(
    uint32_t smem_base, int stage,
    const __half* __restrict__ Ag, const __half* __restrict__ Bg,
    int K, int c, int tid)
{
    const int kk = c * 64;
    // A tile: 128 rows x 8 units
#pragma unroll
    for (int i = 0; i < 4; i++) {
        const int L = tid + i * 256;          // 0..1023
        const int row = L >> 3;
        const int unit = L & 7;
        const uint32_t sw = SMEM_SWIZZLE_128B((uint32_t)(row * 128 + unit * 16));
        const __half* ap = Ag + (size_t)row * K + kk + unit * 8;
        asm volatile("cp.async.cg.shared.global [%0], [%1], 16;"
                     :: "r"(smem_base + HG_A_OFF(stage) + sw), "l"(ap));
    }
    // B tile: 256 rows x 8 units
#pragma unroll
    for (int i = 0; i < 8; i++) {
        const int L = tid + i * 256;          // 0..2047
        const int row = L >> 3;
        const int unit = L & 7;
        const uint32_t sw = SMEM_SWIZZLE_128B((uint32_t)(row * 128 + unit * 16));
        const __half* bp = Bg + (size_t)row * K + kk + unit * 8;
        asm volatile("cp.async.cg.shared.global [%0], [%1], 16;"
                     :: "r"(smem_base + HG_B_OFF(stage) + sw), "l"(bp));
    }
    asm volatile("cp.async.commit_group;");
}

template <int EPI>
__global__ __launch_bounds__(256) void h_gemm(
    int M, int N, int K,
    const __half* __restrict__ A,
    const __half* __restrict__ Bt,
    const float* __restrict__ bias,
    const float* __restrict__ res,
    void* __restrict__ Cv)
{
    extern __shared__ char smem[];
    const uint32_t smem_base = smem_u32(smem);

    const int tid  = threadIdx.x;
    const int lane = tid & 31;
    const int wid  = tid >> 5;
    const int m_w  = (wid >> 2) * 64;   // warp M origin (0 or 64)
    const int n_w  = (wid & 3) * 64;    // warp N origin (0/64/128/192)

    const __half* Ag = A  + (size_t)(blockIdx.y * 128) * K;
    const __half* Bg = Bt + (size_t)(blockIdx.x * 256) * K;

    float acc[4][8][4];
#pragma unroll
    for (int i = 0; i < 4; i++)
#pragma unroll
        for (int j = 0; j < 8; j++)
#pragma unroll
            for (int q = 0; q < 4; q++) acc[i][j][q] = 0.f;

    const int lr  = lane & 7;
    const int lm8 = ((lane >> 3) & 1) * 8;
    const int ub  = lane >> 4;                 // 16B unit select (0/1)
    const int rowA = m_w + lr + lm8;           // + mf*16
    const int rowB = n_w + lr + lm8;           // + nt*16

    const int nk = K >> 6;

    hg_load_chunk(smem_base, 0, Ag, Bg, K, 0, tid);
    hg_load_chunk(smem_base, 1, Ag, Bg, K, 1, tid);
    hg_load_chunk(smem_base, 2, Ag, Bg, K, 2, tid);

    for (int c = 0; c < nk; c++) {
        const int st = c & 3;
        if (c + 3 < nk) {
            hg_load_chunk(smem_base, (c + 3) & 3, Ag, Bg, K, c + 3, tid);
            asm volatile("cp.async.wait_group 3;");
        } else if (c + 2 < nk) {
            asm volatile("cp.async.wait_group 2;");
        } else if (c + 1 < nk) {
            asm volatile("cp.async.wait_group 1;");
        } else {
            asm volatile("cp.async.wait_group 0;");
        }
        __syncthreads();

        const uint32_t aT = smem_base + HG_A_OFF(st);
        const uint32_t bT = smem_base + HG_B_OFF(st);

#pragma unroll
        for (int ks = 0; ks < 4; ks++) {
            const int u = ks * 2 + ub;
            unsigned av[4][4];
#pragma unroll
            for (int mf = 0; mf < 4; mf++) {
                const uint32_t off = (uint32_t)((rowA + mf * 16) * 128 + u * 16);
                ldsm4(av[mf][0], av[mf][1], av[mf][2], av[mf][3],
                      aT + SMEM_SWIZZLE_128B(off));
            }
            unsigned bv[4][4];
#pragma unroll
            for (int nt = 0; nt < 4; nt++) {
                const uint32_t off = (uint32_t)((rowB + nt * 16) * 128 + u * 16);
                ldsm4(bv[nt][0], bv[nt][1], bv[nt][2], bv[nt][3],
                      bT + SMEM_SWIZZLE_128B(off));
            }
#pragma unroll
            for (int mf = 0; mf < 4; mf++)
#pragma unroll
                for (int nt = 0; nt < 4; nt++) {
                    mma_f16(acc[mf][nt * 2 + 0],
                            av[mf][0], av[mf][1], av[mf][2], av[mf][3],
                            bv[nt][0], bv[nt][2]);
                    mma_f16(acc[mf][nt * 2 + 1],
                            av[mf][0], av[mf][1], av[mf][2], av[mf][3],
                            bv[nt][1], bv[nt][3]);
                }
        }
        __syncthreads();
    }

    // ---------------- epilogue ----------------
    float*  Cf = (float*)Cv;
    __half* Ch = (__half*)Cv;
    const int row0 = blockIdx.y * 128 + m_w;
    const int col0 = blockIdx.x * 256 + n_w;

#pragma unroll
    for (int mf = 0; mf < 4; mf++) {
#pragma unroll
        for (int nf = 0; nf < 8; nf++) {
            const int r = row0 + mf * 16 + (lane >> 2);
            const int c = col0 + nf * 8 + (lane & 3) * 2;
            float b0 = 0.f, b1 = 0.f;
            if (EPI == 2 || EPI == 3) { b0 = bias[c]; b1 = bias[c + 1]; }
#pragma unroll
            for (int half = 0; half < 2; half++) {
                const int rr = r + half * 8;
                float v0 = acc[mf][nf][half * 2 + 0];
                float v1 = acc[mf][nf][half * 2 + 1];
                if (EPI == 2) {
                    v0 = gelu_tanh(v0 + b0);
                    v1 = gelu_tanh(v1 + b1);
                    *reinterpret_cast<__half2*>(Ch + (size_t)rr * N + c) =
                        __floats2half2_rn(v0, v1);
                } else {
                    if (EPI == 3) { v0 += b0; v1 += b1; }
                    if (EPI == 1 || EPI == 3) {
                        const float2 rv = *reinterpret_cast<const float2*>(
                            res + (size_t)rr * N + c);
                        v0 += rv.x; v1 += rv.y;
                    }
                    float2 o; o.x = v0; o.y = v1;
                    *reinterpret_cast<float2*>(Cf + (size_t)rr * N + c) = o;
                }
            }
        }
    }
}

// ---------------------------------------------------------------------------
// Tensor-core causal flash attention (R7-validated; fp16 output)
// ---------------------------------------------------------------------------
#define FST 68
#define ATT_SMEM ((128 + 64 + 64 + 128) * FST * (int)sizeof(float))  // 104448

__global__ __launch_bounds__(256) void attn_tc_kernel(
    const float* __restrict__ qkv,
    __half* __restrict__ y)
{
    extern __shared__ float sm[];
    float* Qs = sm;                    // [128][FST]
    float* Ks = Qs + 128 * FST;        // [64][FST]
    float* Vs = Ks + 64 * FST;         // [64][FST]
    float* Ps = Vs + 64 * FST;         // [128][FST]
    const uint32_t Qs_u = smem_u32(Qs);
    const uint32_t Ps_u = smem_u32(Ps);

    const int qt  = blockIdx.x;
    const int bh  = blockIdx.y;
    const int b   = bh >> 4;
    const int h   = bh & 15;
    const int tid = threadIdx.x;
    const int lane = tid & 31;
    const int wid  = tid >> 5;

    const size_t rstr = 3 * DMODEL;
    const float* qbase = qkv + ((size_t)b * SEQ + qt * 128) * rstr + h * HDIM;
    const float* kbase = qkv + (size_t)b * SEQ * rstr + DMODEL     + h * HDIM;
    const float* vbase = qkv + (size_t)b * SEQ * rstr + 2 * DMODEL + h * HDIM;

#pragma unroll
    for (int i = 0; i < 8; i++) {
        int idx = tid + i * 256;
        int r = idx >> 4, c4 = (idx & 15) * 4;
        float4 v = *reinterpret_cast<const float4*>(qbase + (size_t)r * rstr + c4);
        Qs[r * FST + c4 + 0] = roundtf32(v.x * 0.125f);
        Qs[r * FST + c4 + 1] = roundtf32(v.y * 0.125f);
        Qs[r * FST + c4 + 2] = roundtf32(v.z * 0.125f);
        Qs[r * FST + c4 + 3] = roundtf32(v.w * 0.125f);
    }

    float m0 = -1e30f, m1 = -1e30f, l0 = 0.f, l1 = 0.f;
    float acc[8][4];
#pragma unroll
    for (int nf = 0; nf < 8; nf++)
#pragma unroll
        for (int q = 0; q < 4; q++) acc[nf][q] = 0.f;

    const int lr  = lane & 7;
    const int lm8 = ((lane >> 3) & 1) * 8;
    const int lc4 = (lane >> 4) * 4;
    const uint32_t aQ = Qs_u + (uint32_t)((wid * 16 + lr + lm8) * FST + lc4) * 4u;
    const uint32_t aP = Ps_u + (uint32_t)((wid * 16 + lr + lm8) * FST + lc4) * 4u;
    const int q0w = qt * 128 + wid * 16;
    const int nkv = 2 * qt + 2;

    for (int kt = 0; kt < nkv; kt++) {
        __syncthreads();
#pragma unroll
        for (int i = 0; i < 4; i++) {
            int idx = tid + i * 256;
            int r = idx >> 4, c4 = (idx & 15) * 4;
            size_t grow = (size_t)(kt * 64 + r) * rstr + c4;
            float4 k4 = *reinterpret_cast<const float4*>(kbase + grow);
            float4 v4 = *reinterpret_cast<const float4*>(vbase + grow);
            float4 ko, vo;
            ko.x = roundtf32(k4.x); ko.y = roundtf32(k4.y);
            ko.z = roundtf32(k4.z); ko.w = roundtf32(k4.w);
            vo.x = roundtf32(v4.x); vo.y = roundtf32(v4.y);
            vo.z = roundtf32(v4.z); vo.w = roundtf32(v4.w);
            *reinterpret_cast<float4*>(&Ks[r * FST + c4]) = ko;
            *reinterpret_cast<float4*>(&Vs[r * FST + c4]) = vo;
        }
        __syncthreads();

        if (kt * 64 <= q0w + 15) {
            float s[8][4];
#pragma unroll
            for (int nf = 0; nf < 8; nf++)
#pragma unroll
                for (int q = 0; q < 4; q++) s[nf][q] = 0.f;

#pragma unroll
            for (int kk = 0; kk < 8; kk++) {
                unsigned a0, a1, a2, a3;
                ldsm4(a0, a1, a2, a3, aQ + (uint32_t)(kk * 8) * 4u);
#pragma unroll
                for (int nf = 0; nf < 8; nf++) {
                    const float* kp = &Ks[(nf * 8 + (lane >> 2)) * FST
                                          + kk * 8 + (lane & 3)];
                    unsigned b0 = __float_as_uint(kp[0]);
                    unsigned b1 = __float_as_uint(kp[4]);
                    mma_tf32(s[nf], a0, a1, a2, a3, b0, b1);
                }
            }

            if (kt >= 2 * qt) {
                const int r_lo = q0w + (lane >> 2);
#pragma unroll
                for (int nf = 0; nf < 8; nf++) {
                    int kg = kt * 64 + nf * 8 + 2 * (lane & 3);
                    if (kg     > r_lo)     s[nf][0] = -1e30f;
                    if (kg + 1 > r_lo)     s[nf][1] = -1e30f;
                    if (kg     > r_lo + 8) s[nf][2] = -1e30f;
                    if (kg + 1 > r_lo + 8) s[nf][3] = -1e30f;
                }
            }

            float mx0 = -1e30f, mx1 = -1e30f;
#pragma unroll
            for (int nf = 0; nf < 8; nf++) {
                mx0 = fmaxf(mx0, fmaxf(s[nf][0], s[nf][1]));
                mx1 = fmaxf(mx1, fmaxf(s[nf][2], s[nf][3]));
            }
            mx0 = fmaxf(mx0, __shfl_xor_sync(0xffffffffu, mx0, 1));
            mx0 = fmaxf(mx0, __shfl_xor_sync(0xffffffffu, mx0, 2));
            mx1 = fmaxf(mx1, __shfl_xor_sync(0xffffffffu, mx1, 1));
            mx1 = fmaxf(mx1, __shfl_xor_sync(0xffffffffu, mx1, 2));

            const float mn0 = fmaxf(m0, mx0);
            const float mn1 = fmaxf(m1, mx1);
            const float cor0 = __expf(m0 - mn0);
            const float cor1 = __expf(m1 - mn1);
            float sum0 = 0.f, sum1 = 0.f;
            const int prow = (wid * 16 + (lane >> 2)) * FST + 2 * (lane & 3);
#pragma unroll
            for (int nf = 0; nf < 8; nf++) {
                float p0 = __expf(s[nf][0] - mn0);
                float p1 = __expf(s[nf][1] - mn0);
                float p2 = __expf(s[nf][2] - mn1);
                float p3 = __expf(s[nf][3] - mn1);
                sum0 += p0 + p1;
                sum1 += p2 + p3;
                float2 w0; w0.x = roundtf32(p0); w0.y = roundtf32(p1);
                float2 w1; w1.x = roundtf32(p2); w1.y = roundtf32(p3);
                *reinterpret_cast<float2*>(&Ps[prow + nf * 8]) = w0;
                *reinterpret_cast<float2*>(&Ps[prow + 8 * FST + nf * 8]) = w1;
            }
            sum0 += __shfl_xor_sync(0xffffffffu, sum0, 1);
            sum0 += __shfl_xor_sync(0xffffffffu, sum0, 2);
            sum1 += __shfl_xor_sync(0xffffffffu, sum1, 1);
            sum1 += __shfl_xor_sync(0xffffffffu, sum1, 2);

            l0 = l0 * cor0 + sum0;
            l1 = l1 * cor1 + sum1;
            m0 = mn0; m1 = mn1;
#pragma unroll
            for (int nf = 0; nf < 8; nf++) {
                acc[nf][0] *= cor0; acc[nf][1] *= cor0;
                acc[nf][2] *= cor1; acc[nf][3] *= cor1;
            }
            __syncwarp();

#pragma unroll
            for (int kk = 0; kk < 8; kk++) {
                unsigned a0, a1, a2, a3;
                ldsm4(a0, a1, a2, a3, aP + (uint32_t)(kk * 8) * 4u);
#pragma unroll
                for (int nf = 0; nf < 8; nf++) {
                    const float* vp = &Vs[(kk * 8 + (lane & 3)) * FST
                                          + nf * 8 + (lane >> 2)];
                    unsigned b0 = __float_as_uint(vp[0]);
                    unsigned b1 = __float_as_uint(vp[4 * FST]);
                    mma_tf32(acc[nf], a0, a1, a2, a3, b0, b1);
                }
            }
            __syncwarp();
        }
    }

    const float inv0 = 1.0f / l0;
    const float inv1 = 1.0f / l1;
    const size_t row_lo = (size_t)b * SEQ + qt * 128 + wid * 16 + (lane >> 2);
#pragma unroll
    for (int nf = 0; nf < 8; nf++) {
        const int col = h * HDIM + nf * 8 + 2 * (lane & 3);
        *reinterpret_cast<__half2*>(&y[row_lo * DMODEL + col]) =
            __floats2half2_rn(acc[nf][0] * inv0, acc[nf][1] * inv0);
        *reinterpret_cast<__half2*>(&y[(row_lo + 8) * DMODEL + col]) =
            __floats2half2_rn(acc[nf][2] * inv1, acc[nf][3] * inv1);
    }
}

// ---------------------------------------------------------------------------
// Launch
// ---------------------------------------------------------------------------
extern "C" void kernel_launch(void* const* d_in, const int* in_sizes, int n_in,
                              void* d_out, int out_size)
{
    const float* x      = (const float*)d_in[0];
    const float* w_attn = (const float*)d_in[1];
    const float* w_o    = (const float*)d_in[2];
    const float* ln1_g  = (const float*)d_in[3];
    const float* ln1_b  = (const float*)d_in[4];
    const float* ln2_g  = (const float*)d_in[5];
    const float* ln2_b  = (const float*)d_in[6];
    const float* w_fc   = (const float*)d_in[7];
    const float* b_fc   = (const float*)d_in[8];
    const float* w_proj = (const float*)d_in[9];
    const float* b_proj = (const float*)d_in[10];
    float* out = (float*)d_out;

    __half *lnh, *yh, *hh, *wa, *wo, *wf, *wp;
    float *qkvp, *x1;
    cudaGetSymbolAddress((void**)&lnh,  g_lnh);
    cudaGetSymbolAddress((void**)&qkvp, g_qkv);
    cudaGetSymbolAddress((void**)&yh,   g_yh);
    cudaGetSymbolAddress((void**)&x1,   g_x1);
    cudaGetSymbolAddress((void**)&hh,   g_hh);
    cudaGetSymbolAddress((void**)&wa,   g_wa);
    cudaGetSymbolAddress((void**)&wo,   g_wo);
    cudaGetSymbolAddress((void**)&wf,   g_wf);
    cudaGetSymbolAddress((void**)&wp,   g_wp);

    cudaFuncSetAttribute(attn_tc_kernel,
                         cudaFuncAttributeMaxDynamicSharedMemorySize, ATT_SMEM);
    cudaFuncSetAttribute(h_gemm<0>,
                         cudaFuncAttributeMaxDynamicSharedMemorySize, HG_SMEM);
    cudaFuncSetAttribute(h_gemm<1>,
                         cudaFuncAttributeMaxDynamicSharedMemorySize, HG_SMEM);
    cudaFuncSetAttribute(h_gemm<2>,
                         cudaFuncAttributeMaxDynamicSharedMemorySize, HG_SMEM);
    cudaFuncSetAttribute(h_gemm<3>,
                         cudaFuncAttributeMaxDynamicSharedMemorySize, HG_SMEM);

    // 0) transpose + fp16-convert weights (once per launch)
    transpose_h_kernel<<<dim3(3 * DMODEL / 32, DMODEL / 32), dim3(32, 8)>>>(
        w_attn, wa, DMODEL, 3 * DMODEL);
    transpose_h_kernel<<<dim3(DMODEL / 32, DMODEL / 32), dim3(32, 8)>>>(
        w_o, wo, DMODEL, DMODEL);
    transpose_h_kernel<<<dim3(4 * DMODEL / 32, DMODEL / 32), dim3(32, 8)>>>(
        w_fc, wf, DMODEL, 4 * DMODEL);
    transpose_h_kernel<<<dim3(DMODEL / 32, 4 * DMODEL / 32), dim3(32, 8)>>>(
        w_proj, wp, 4 * DMODEL, DMODEL);

    // 1) ln1 -> fp16
    ln_kernel<<<ROWS, 256>>>(x, ln1_g, ln1_b, lnh);
    // 2) qkv = ln1 @ w_attn        [8192 x 3072] fp32 out
    h_gemm<0><<<dim3(3 * DMODEL / 256, ROWS / 128), 256, HG_SMEM>>>(
        ROWS, 3 * DMODEL, DMODEL, lnh, wa, nullptr, nullptr, qkvp);
    // 3) attention -> y (fp16)
    attn_tc_kernel<<<dim3(SEQ / 128, BATCH * NHEAD), 256, ATT_SMEM>>>(qkvp, yh);
    // 4) x1 = x + y @ w_o          fp32 out
    h_gemm<1><<<dim3(DMODEL / 256, ROWS / 128), 256, HG_SMEM>>>(
        ROWS, DMODEL, DMODEL, yh, wo, nullptr, x, x1);
    // 5) ln2 -> fp16
    ln_kernel<<<ROWS, 256>>>(x1, ln2_g, ln2_b, lnh);
    // 6) h = gelu(ln2 @ w_fc + b_fc)   [8192 x 4096] fp16 out
    h_gemm<2><<<dim3(4 * DMODEL / 256, ROWS / 128), 256, HG_SMEM>>>(
        ROWS, 4 * DMODEL, DMODEL, lnh, wf, b_fc, nullptr, hh);
    // 7) out = x1 + h @ w_proj + b_proj   fp32 out
    h_gemm<3><<<dim3(DMODEL / 256, ROWS / 128), 256, HG_SMEM>>>(
        ROWS, DMODEL, 4 * DMODEL, hh, wp, b_proj, x1, out);
}

// round 12
// speedup vs baseline: 1.2246x; 1.2246x over previous
#include <cuda_runtime.h>
#include <cuda_fp16.h>
#include <math.h>
#include <stdint.h>

// ---------------------------------------------------------------------------
// Problem constants
// ---------------------------------------------------------------------------
#define BATCH 4
#define SEQ   2048
#define DMODEL 1024
#define NHEAD 16
#define HDIM  64
#define ROWS  (BATCH * SEQ)          // 8192
#define EPS   1e-5f

// ---------------------------------------------------------------------------
// Scratch buffers (static device globals: allocation-free per harness rules)
// ---------------------------------------------------------------------------
__device__ __half g_lnh[ROWS * DMODEL];       // 16 MB  LN output (fp16, GEMM A)
__device__ __half g_qkv[ROWS * 3 * DMODEL];   // 48 MB  qkv (fp16)
__device__ __half g_yh [ROWS * DMODEL];       // 16 MB  attention out (fp16)
__device__ float  g_x1 [ROWS * DMODEL];       // 32 MB  residual after attn
__device__ __half g_hh [ROWS * 4 * DMODEL];   // 64 MB  MLP hidden (fp16)
// fp16, TRANSPOSED weights [N][K]
__device__ __half g_wa [3 * DMODEL * DMODEL]; // 6 MB
__device__ __half g_wo [DMODEL * DMODEL];     // 2 MB
__device__ __half g_wf [4 * DMODEL * DMODEL]; // 8 MB
__device__ __half g_wp [DMODEL * 4 * DMODEL]; // 8 MB

// ---------------------------------------------------------------------------
// Helpers
// ---------------------------------------------------------------------------
__device__ __forceinline__ uint32_t smem_u32(const void* p) {
    uint32_t a;
    asm("{ .reg .u64 t; cvta.to.shared.u64 t, %1; cvt.u32.u64 %0, t; }"
        : "=r"(a) : "l"(p));
    return a;
}

#define SMEM_SWIZZLE_128B(off) ((off) ^ (((off) >> 3) & 0x70))

__device__ __forceinline__ void ldsm4(unsigned& r0, unsigned& r1,
                                      unsigned& r2, unsigned& r3, uint32_t a) {
    asm volatile("ldmatrix.sync.aligned.m8n8.x4.shared.b16 {%0,%1,%2,%3}, [%4];"
                 : "=r"(r0), "=r"(r1), "=r"(r2), "=r"(r3) : "r"(a));
}

__device__ __forceinline__ void ldsm4_t(unsigned& r0, unsigned& r1,
                                        unsigned& r2, unsigned& r3, uint32_t a) {
    asm volatile("ldmatrix.sync.aligned.m8n8.x4.trans.shared.b16 {%0,%1,%2,%3}, [%4];"
                 : "=r"(r0), "=r"(r1), "=r"(r2), "=r"(r3) : "r"(a));
}

__device__ __forceinline__ void mma_f16(float* c,
                                        unsigned a0, unsigned a1,
                                        unsigned a2, unsigned a3,
                                        unsigned b0, unsigned b1) {
    asm volatile(
        "mma.sync.aligned.m16n8k16.row.col.f32.f16.f16.f32 "
        "{%0,%1,%2,%3}, {%4,%5,%6,%7}, {%8,%9}, {%0,%1,%2,%3};"
        : "+f"(c[0]), "+f"(c[1]), "+f"(c[2]), "+f"(c[3])
        : "r"(a0), "r"(a1), "r"(a2), "r"(a3), "r"(b0), "r"(b1));
}

__device__ __forceinline__ float gelu_tanh(float x) {
    const float c0 = 0.7978845608028654f;  // sqrt(2/pi)
    const float c1 = 0.044715f;
    float t = tanhf(c0 * (x + c1 * x * x * x));
    return 0.5f * x * (1.0f + t);
}

// Transpose + fp16-convert a weight matrix: in [K][N] fp32 -> out [N][K] fp16
__global__ __launch_bounds__(256) void transpose_h_kernel(
    const float* __restrict__ in, __half* __restrict__ out, int K, int N)
{
    __shared__ float t[32][33];
    const int n0 = blockIdx.x * 32;
    const int k0 = blockIdx.y * 32;
    const int tx = threadIdx.x, ty = threadIdx.y;
#pragma unroll
    for (int i = 0; i < 4; i++)
        t[ty + 8 * i][tx] = in[(size_t)(k0 + ty + 8 * i) * N + n0 + tx];
    __syncthreads();
#pragma unroll
    for (int i = 0; i < 4; i++)
        out[(size_t)(n0 + ty + 8 * i) * K + k0 + tx] =
            __float2half_rn(t[tx][ty + 8 * i]);
}

// ---------------------------------------------------------------------------
// LayerNorm: fp32 in, fp16 out
// ---------------------------------------------------------------------------
__device__ __forceinline__ float warp_sum(float v) {
#pragma unroll
    for (int o = 16; o > 0; o >>= 1) v += __shfl_xor_sync(0xffffffffu, v, o);
    return v;
}

__global__ __launch_bounds__(256) void ln_kernel(
    const float* __restrict__ x,
    const float* __restrict__ g,
    const float* __restrict__ b,
    __half* __restrict__ out)
{
    const int row = blockIdx.x;
    const int tid = threadIdx.x;
    const float4 v = reinterpret_cast<const float4*>(x + (size_t)row * DMODEL)[tid];

    float s  = v.x + v.y + v.z + v.w;
    float ss = v.x*v.x + v.y*v.y + v.z*v.z + v.w*v.w;
    s  = warp_sum(s);
    ss = warp_sum(ss);

    __shared__ float red0[8], red1[8];
    const int wid = tid >> 5, lane = tid & 31;
    if (lane == 0) { red0[wid] = s; red1[wid] = ss; }
    __syncthreads();
    float ts = 0.f, tss = 0.f;
#pragma unroll
    for (int w = 0; w < 8; w++) { ts += red0[w]; tss += red1[w]; }

    const float mean = ts * (1.0f / DMODEL);
    const float var  = tss * (1.0f / DMODEL) - mean * mean;
    const float rstd = rsqrtf(var + EPS);

    const float4 gv = reinterpret_cast<const float4*>(g)[tid];
    const float4 bv = reinterpret_cast<const float4*>(b)[tid];
    __half2 h0 = __floats2half2_rn((v.x - mean) * rstd * gv.x + bv.x,
                                   (v.y - mean) * rstd * gv.y + bv.y);
    __half2 h1 = __floats2half2_rn((v.z - mean) * rstd * gv.z + bv.z,
                                   (v.w - mean) * rstd * gv.w + bv.w);
    __half2* op = reinterpret_cast<__half2*>(out + (size_t)row * DMODEL);
    op[tid * 2 + 0] = h0;
    op[tid * 2 + 1] = h1;
}

// ---------------------------------------------------------------------------
// FP16 tensor-core GEMM (R10 config: 128x128, BK=64, 3-stage, 2 CTAs/SM)
// with single-syncthreads pipeline (prefetch issued AFTER the barrier).
// EPI: 0 none(f32) | 1 +res(f32) | 2 gelu(acc+bias)->fp16 | 3 +bias+res(f32)
//      4 plain fp16 out
// ---------------------------------------------------------------------------
#define HG_TILE 16384                        // 128 rows x 128 bytes
#define HG_A_OFF(s) ((s) * 2 * HG_TILE)
#define HG_B_OFF(s) ((s) * 2 * HG_TILE + HG_TILE)
#define HG_SMEM (3 * 2 * HG_TILE)            // 98304 B

__device__ __forceinline__ void hg_load_chunk(
    uint32_t smem_base, int stage,
    const __half* __restrict__ Ag, const __half* __restrict__ Bg,
    int K, int c, int tid)
{
    const int kk = c * 64;
#pragma unroll
    for (int i = 0; i < 4; i++) {
        const int L = tid + i * 256;          // 0..1023
        const int row = L >> 3;
        const int unit = L & 7;
        const uint32_t sw = SMEM_SWIZZLE_128B((uint32_t)(row * 128 + unit * 16));
        const __half* ap = Ag + (size_t)row * K + kk + unit * 8;
        const __half* bp = Bg + (size_t)row * K + kk + unit * 8;
        asm volatile("cp.async.cg.shared.global [%0], [%1], 16;"
                     :: "r"(smem_base + HG_A_OFF(stage) + sw), "l"(ap));
        asm volatile("cp.async.cg.shared.global [%0], [%1], 16;"
                     :: "r"(smem_base + HG_B_OFF(stage) + sw), "l"(bp));
    }
    asm volatile("cp.async.commit_group;");
}

template <int EPI>
__global__ __launch_bounds__(256, 2) void h_gemm(
    int M, int N, int K,
    const __half* __restrict__ A,
    const __half* __restrict__ Bt,
    const float* __restrict__ bias,
    const float* __restrict__ res,
    void* __restrict__ Cv)
{
    extern __shared__ char smem[];
    const uint32_t smem_base = smem_u32(smem);

    const int tid  = threadIdx.x;
    const int lane = tid & 31;
    const int wid  = tid >> 5;
    const int m_w  = (wid >> 2) * 64;   // warp M origin (0 or 64)
    const int n_w  = (wid & 3) * 32;    // warp N origin

    const __half* Ag = A  + (size_t)(blockIdx.y * 128) * K;
    const __half* Bg = Bt + (size_t)(blockIdx.x * 128) * K;

    float acc[4][4][4];
#pragma unroll
    for (int i = 0; i < 4; i++)
#pragma unroll
        for (int j = 0; j < 4; j++)
#pragma unroll
            for (int q = 0; q < 4; q++) acc[i][j][q] = 0.f;

    const int lr  = lane & 7;
    const int lm8 = ((lane >> 3) & 1) * 8;
    const int ub  = lane >> 4;                 // 16B unit select (0/1)
    const int rowA = m_w + lr + lm8;           // + mf*16
    const int rowB = n_w + lr + lm8;           // + nt*16

    const int nk = K >> 6;

    hg_load_chunk(smem_base, 0, Ag, Bg, K, 0, tid);
    hg_load_chunk(smem_base, 1, Ag, Bg, K, 1, tid);

    int st = 0, ld = 2;
    for (int c = 0; c < nk; c++) {
        if (c + 1 < nk) {
            asm volatile("cp.async.wait_group 1;");
        } else {
            asm volatile("cp.async.wait_group 0;");
        }
        __syncthreads();
        if (c + 2 < nk) {
            hg_load_chunk(smem_base, ld, Ag, Bg, K, c + 2, tid);
        }

        const uint32_t aT = smem_base + HG_A_OFF(st);
        const uint32_t bT = smem_base + HG_B_OFF(st);

#pragma unroll
        for (int ks = 0; ks < 4; ks++) {
            const int u = ks * 2 + ub;
            unsigned av[4][4];
#pragma unroll
            for (int mf = 0; mf < 4; mf++) {
                const uint32_t off = (uint32_t)((rowA + mf * 16) * 128 + u * 16);
                ldsm4(av[mf][0], av[mf][1], av[mf][2], av[mf][3],
                      aT + SMEM_SWIZZLE_128B(off));
            }
            unsigned bv[2][4];
#pragma unroll
            for (int nt = 0; nt < 2; nt++) {
                const uint32_t off = (uint32_t)((rowB + nt * 16) * 128 + u * 16);
                ldsm4(bv[nt][0], bv[nt][1], bv[nt][2], bv[nt][3],
                      bT + SMEM_SWIZZLE_128B(off));
            }
#pragma unroll
            for (int mf = 0; mf < 4; mf++)
#pragma unroll
                for (int nt = 0; nt < 2; nt++) {
                    mma_f16(acc[mf][nt * 2 + 0],
                            av[mf][0], av[mf][1], av[mf][2], av[mf][3],
                            bv[nt][0], bv[nt][2]);
                    mma_f16(acc[mf][nt * 2 + 1],
                            av[mf][0], av[mf][1], av[mf][2], av[mf][3],
                            bv[nt][1], bv[nt][3]);
                }
        }
        st++; if (st == 3) st = 0;
        ld++; if (ld == 3) ld = 0;
    }

    __syncthreads();   // all reads done before CTA exit overlap (cheap, once)

    // ---------------- epilogue ----------------
    float*  Cf = (float*)Cv;
    __half* Ch = (__half*)Cv;
    const int row0 = blockIdx.y * 128 + m_w;
    const int col0 = blockIdx.x * 128 + n_w;

#pragma unroll
    for (int mf = 0; mf < 4; mf++) {
#pragma unroll
        for (int nf = 0; nf < 4; nf++) {
            const int r = row0 + mf * 16 + (lane >> 2);
            const int c = col0 + nf * 8 + (lane & 3) * 2;
            float b0 = 0.f, b1 = 0.f;
            if (EPI == 2 || EPI == 3) { b0 = bias[c]; b1 = bias[c + 1]; }
#pragma unroll
            for (int half = 0; half < 2; half++) {
                const int rr = r + half * 8;
                float v0 = acc[mf][nf][half * 2 + 0];
                float v1 = acc[mf][nf][half * 2 + 1];
                if (EPI == 2) {
                    v0 = gelu_tanh(v0 + b0);
                    v1 = gelu_tanh(v1 + b1);
                    *reinterpret_cast<__half2*>(Ch + (size_t)rr * N + c) =
                        __floats2half2_rn(v0, v1);
                } else if (EPI == 4) {
                    *reinterpret_cast<__half2*>(Ch + (size_t)rr * N + c) =
                        __floats2half2_rn(v0, v1);
                } else {
                    if (EPI == 3) { v0 += b0; v1 += b1; }
                    if (EPI == 1 || EPI == 3) {
                        const float2 rv = *reinterpret_cast<const float2*>(
                            res + (size_t)rr * N + c);
                        v0 += rv.x; v1 += rv.y;
                    }
                    float2 o; o.x = v0; o.y = v1;
                    *reinterpret_cast<float2*>(Cf + (size_t)rr * N + c) = o;
                }
            }
        }
    }
}

// ---------------------------------------------------------------------------
// Full-fp16 tensor-core causal flash attention.
// Grid: (qtile 0..15, b*H 0..63). Block: 256 threads = 8 warps, warp w owns
// q rows [16w, 16w+16).  All tiles 128B/row, SW128 swizzled (same addressing
// as h_gemm, numerically validated there):
//   Q [128][64]h @0, K [64][64]h @16K, V [64][64]h @24K, P [128][64]h @32K
// S = Q@K^T via mma.f16 (K rows are the validated "Bt" B-operand layout).
// O += P@V via ldmatrix.trans on V (B-pairs (v0,v1)/(v2,v3)).
// ---------------------------------------------------------------------------
#define AQ_OFF 0
#define AK_OFF 16384
#define AV_OFF 24576
#define AP_OFF 32768
#define ATTH_SMEM 49152

__global__ __launch_bounds__(256) void attn_h_kernel(
    const __half* __restrict__ qkv,
    __half* __restrict__ y)
{
    extern __shared__ char smc[];
    const uint32_t sb = smem_u32(smc);

    const int qt  = blockIdx.x;
    const int bh  = blockIdx.y;
    const int b   = bh >> 4;
    const int h   = bh & 15;
    const int tid = threadIdx.x;
    const int lane = tid & 31;
    const int wid  = tid >> 5;

    const size_t rstr = 3 * DMODEL;   // halves
    const __half* qb = qkv + ((size_t)b * SEQ + qt * 128) * rstr + h * HDIM;
    const __half* kb = qkv + (size_t)b * SEQ * rstr + DMODEL     + h * HDIM;
    const __half* vb = qkv + (size_t)b * SEQ * rstr + 2 * DMODEL + h * HDIM;

    // load Q tile, scaled by 1/sqrt(64) = 0.125 (exact in fp16)
    const __half2 qsc = __float2half2_rn(0.125f);
#pragma unroll
    for (int i = 0; i < 4; i++) {
        const int L = tid + i * 256;       // 0..1023
        const int row = L >> 3, unit = L & 7;
        uint4 t = *reinterpret_cast<const uint4*>(qb + (size_t)row * rstr + unit * 8);
        __half2* tp = reinterpret_cast<__half2*>(&t);
#pragma unroll
        for (int j = 0; j < 4; j++) tp[j] = __hmul2(tp[j], qsc);
        *reinterpret_cast<uint4*>(smc + AQ_OFF +
            SMEM_SWIZZLE_128B((uint32_t)(row * 128 + unit * 16))) = t;
    }

    float m0 = -1e30f, m1 = -1e30f, l0 = 0.f, l1 = 0.f;
    float acc[8][4];
#pragma unroll
    for (int nf = 0; nf < 8; nf++)
#pragma unroll
        for (int q = 0; q < 4; q++) acc[nf][q] = 0.f;

    const int lr  = lane & 7;
    const int lm8 = ((lane >> 3) & 1) * 8;
    const int ub  = lane >> 4;
    const int q0w = qt * 128 + wid * 16;
    const int nkv = 2 * qt + 2;

    for (int kt = 0; kt < nkv; kt++) {
        __syncthreads();   // protect K/V reuse from previous iteration
#pragma unroll
        for (int i = 0; i < 2; i++) {
            const int L = tid + i * 256;   // 0..511
            const int row = L >> 3, unit = L & 7;
            const size_t src = (size_t)(kt * 64 + row) * rstr + unit * 8;
            const uint32_t sw = SMEM_SWIZZLE_128B((uint32_t)(row * 128 + unit * 16));
            *reinterpret_cast<uint4*>(smc + AK_OFF + sw) =
                *reinterpret_cast<const uint4*>(kb + src);
            *reinterpret_cast<uint4*>(smc + AV_OFF + sw) =
                *reinterpret_cast<const uint4*>(vb + src);
        }
        __syncthreads();

        if (kt * 64 <= q0w + 15) {   // warp not fully masked
            // ---- S = Q @ K^T (warp tile 16 x 64) ----
            float s[8][4];
#pragma unroll
            for (int nf = 0; nf < 8; nf++)
#pragma unroll
                for (int q = 0; q < 4; q++) s[nf][q] = 0.f;

#pragma unroll
            for (int ks = 0; ks < 4; ks++) {
                const int u = ks * 2 + ub;
                unsigned a0, a1, a2, a3;
                ldsm4(a0, a1, a2, a3, sb + AQ_OFF + SMEM_SWIZZLE_128B(
                    (uint32_t)((wid * 16 + lr + lm8) * 128 + u * 16)));
#pragma unroll
                for (int nt = 0; nt < 4; nt++) {
                    unsigned b0, b1, b2, b3;
                    ldsm4(b0, b1, b2, b3, sb + AK_OFF + SMEM_SWIZZLE_128B(
                        (uint32_t)((nt * 16 + lr + lm8) * 128 + u * 16)));
                    mma_f16(s[nt * 2 + 0], a0, a1, a2, a3, b0, b2);
                    mma_f16(s[nt * 2 + 1], a0, a1, a2, a3, b1, b3);
                }
            }

            // ---- causal mask (diagonal tiles only) ----
            if (kt >= 2 * qt) {
                const int r_lo = q0w + (lane >> 2);
#pragma unroll
                for (int nf = 0; nf < 8; nf++) {
                    int kg = kt * 64 + nf * 8 + 2 * (lane & 3);
                    if (kg     > r_lo)     s[nf][0] = -1e30f;
                    if (kg + 1 > r_lo)     s[nf][1] = -1e30f;
                    if (kg     > r_lo + 8) s[nf][2] = -1e30f;
                    if (kg + 1 > r_lo + 8) s[nf][3] = -1e30f;
                }
            }

            // ---- online softmax (rows lane>>2 and +8; quad shfl reduce) ----
            float mx0 = -1e30f, mx1 = -1e30f;
#pragma unroll
            for (int nf = 0; nf < 8; nf++) {
                mx0 = fmaxf(mx0, fmaxf(s[nf][0], s[nf][1]));
                mx1 = fmaxf(mx1, fmaxf(s[nf][2], s[nf][3]));
            }
            mx0 = fmaxf(mx0, __shfl_xor_sync(0xffffffffu, mx0, 1));
            mx0 = fmaxf(mx0, __shfl_xor_sync(0xffffffffu, mx0, 2));
            mx1 = fmaxf(mx1, __shfl_xor_sync(0xffffffffu, mx1, 1));
            mx1 = fmaxf(mx1, __shfl_xor_sync(0xffffffffu, mx1, 2));

            const float mn0 = fmaxf(m0, mx0);
            const float mn1 = fmaxf(m1, mx1);
            const float cor0 = __expf(m0 - mn0);
            const float cor1 = __expf(m1 - mn1);
            float sum0 = 0.f, sum1 = 0.f;
            const uint32_t pr0 = (uint32_t)((wid * 16 + (lane >> 2)) * 128
                                            + (lane & 3) * 4);
#pragma unroll
            for (int nf = 0; nf < 8; nf++) {
                float p0 = __expf(s[nf][0] - mn0);
                float p1 = __expf(s[nf][1] - mn0);
                float p2 = __expf(s[nf][2] - mn1);
                float p3 = __expf(s[nf][3] - mn1);
                sum0 += p0 + p1;
                sum1 += p2 + p3;
                *reinterpret_cast<__half2*>(smc + AP_OFF +
                    SMEM_SWIZZLE_128B(pr0 + (uint32_t)(nf * 16))) =
                    __floats2half2_rn(p0, p1);
                *reinterpret_cast<__half2*>(smc + AP_OFF +
                    SMEM_SWIZZLE_128B(pr0 + 8 * 128 + (uint32_t)(nf * 16))) =
                    __floats2half2_rn(p2, p3);
            }
            sum0 += __shfl_xor_sync(0xffffffffu, sum0, 1);
            sum0 += __shfl_xor_sync(0xffffffffu, sum0, 2);
            sum1 += __shfl_xor_sync(0xffffffffu, sum1, 1);
            sum1 += __shfl_xor_sync(0xffffffffu, sum1, 2);

            l0 = l0 * cor0 + sum0;
            l1 = l1 * cor1 + sum1;
            m0 = mn0; m1 = mn1;
#pragma unroll
            for (int nf = 0; nf < 8; nf++) {
                acc[nf][0] *= cor0; acc[nf][1] *= cor0;
                acc[nf][2] *= cor1; acc[nf][3] *= cor1;
            }
            __syncwarp();   // Ps visible to ldmatrix across lanes

            // ---- O += P @ V  (V via ldmatrix.trans) ----
#pragma unroll
            for (int ks = 0; ks < 4; ks++) {
                const int u = ks * 2 + ub;
                unsigned p0, p1, p2, p3;
                ldsm4(p0, p1, p2, p3, sb + AP_OFF + SMEM_SWIZZLE_128B(
                    (uint32_t)((wid * 16 + lr + lm8) * 128 + u * 16)));
#pragma unroll
                for (int nt = 0; nt < 4; nt++) {
                    unsigned v0, v1, v2, v3;
                    ldsm4_t(v0, v1, v2, v3, sb + AV_OFF + SMEM_SWIZZLE_128B(
                        (uint32_t)((ks * 16 + lr + lm8) * 128
                                   + (nt * 2 + ub) * 16)));
                    mma_f16(acc[nt * 2 + 0], p0, p1, p2, p3, v0, v1);
                    mma_f16(acc[nt * 2 + 1], p0, p1, p2, p3, v2, v3);
                }
            }
            __syncwarp();   // PV reads done before next iter's Ps writes
        }
    }

    // ---- normalize + write fp16 ----
    const float inv0 = 1.0f / l0;
    const float inv1 = 1.0f / l1;
    const size_t row_lo = (size_t)b * SEQ + qt * 128 + wid * 16 + (lane >> 2);
#pragma unroll
    for (int nf = 0; nf < 8; nf++) {
        const int col = h * HDIM + nf * 8 + 2 * (lane & 3);
        *reinterpret_cast<__half2*>(&y[row_lo * DMODEL + col]) =
            __floats2half2_rn(acc[nf][0] * inv0, acc[nf][1] * inv0);
        *reinterpret_cast<__half2*>(&y[(row_lo + 8) * DMODEL + col]) =
            __floats2half2_rn(acc[nf][2] * inv1, acc[nf][3] * inv1);
    }
}

// ---------------------------------------------------------------------------
// Launch
// ---------------------------------------------------------------------------
extern "C" void kernel_launch(void* const* d_in, const int* in_sizes, int n_in,
                              void* d_out, int out_size)
{
    const float* x      = (const float*)d_in[0];
    const float* w_attn = (const float*)d_in[1];
    const float* w_o    = (const float*)d_in[2];
    const float* ln1_g  = (const float*)d_in[3];
    const float* ln1_b  = (const float*)d_in[4];
    const float* ln2_g  = (const float*)d_in[5];
    const float* ln2_b  = (const float*)d_in[6];
    const float* w_fc   = (const float*)d_in[7];
    const float* b_fc   = (const float*)d_in[8];
    const float* w_proj = (const float*)d_in[9];
    const float* b_proj = (const float*)d_in[10];
    float* out = (float*)d_out;

    __half *lnh, *qkvp, *yh, *hh, *wa, *wo, *wf, *wp;
    float *x1;
    cudaGetSymbolAddress((void**)&lnh,  g_lnh);
    cudaGetSymbolAddress((void**)&qkvp, g_qkv);
    cudaGetSymbolAddress((void**)&yh,   g_yh);
    cudaGetSymbolAddress((void**)&x1,   g_x1);
    cudaGetSymbolAddress((void**)&hh,   g_hh);
    cudaGetSymbolAddress((void**)&wa,   g_wa);
    cudaGetSymbolAddress((void**)&wo,   g_wo);
    cudaGetSymbolAddress((void**)&wf,   g_wf);
    cudaGetSymbolAddress((void**)&wp,   g_wp);

    cudaFuncSetAttribute(attn_h_kernel,
                         cudaFuncAttributeMaxDynamicSharedMemorySize, ATTH_SMEM);
    cudaFuncSetAttribute(h_gemm<0>,
                         cudaFuncAttributeMaxDynamicSharedMemorySize, HG_SMEM);
    cudaFuncSetAttribute(h_gemm<1>,
                         cudaFuncAttributeMaxDynamicSharedMemorySize, HG_SMEM);
    cudaFuncSetAttribute(h_gemm<2>,
                         cudaFuncAttributeMaxDynamicSharedMemorySize, HG_SMEM);
    cudaFuncSetAttribute(h_gemm<3>,
                         cudaFuncAttributeMaxDynamicSharedMemorySize, HG_SMEM);
    cudaFuncSetAttribute(h_gemm<4>,
                         cudaFuncAttributeMaxDynamicSharedMemorySize, HG_SMEM);

    // 0) transpose + fp16-convert weights (once per launch)
    transpose_h_kernel<<<dim3(3 * DMODEL / 32, DMODEL / 32), dim3(32, 8)>>>(
        w_attn, wa, DMODEL, 3 * DMODEL);
    transpose_h_kernel<<<dim3(DMODEL / 32, DMODEL / 32), dim3(32, 8)>>>(
        w_o, wo, DMODEL, DMODEL);
    transpose_h_kernel<<<dim3(4 * DMODEL / 32, DMODEL / 32), dim3(32, 8)>>>(
        w_fc, wf, DMODEL, 4 * DMODEL);
    transpose_h_kernel<<<dim3(DMODEL / 32, 4 * DMODEL / 32), dim3(32, 8)>>>(
        w_proj, wp, 4 * DMODEL, DMODEL);

    // 1) ln1 -> fp16
    ln_kernel<<<ROWS, 256>>>(x, ln1_g, ln1_b, lnh);
    // 2) qkv = ln1 @ w_attn        [8192 x 3072] fp16 out
    h_gemm<4><<<dim3(3 * DMODEL / 128, ROWS / 128), 256, HG_SMEM>>>(
        ROWS, 3 * DMODEL, DMODEL, lnh, wa, nullptr, nullptr, qkvp);
    // 3) attention -> y (fp16, full-fp16 mma)
    attn_h_kernel<<<dim3(SEQ / 128, BATCH * NHEAD), 256, ATTH_SMEM>>>(qkvp, yh);
    // 4) x1 = x + y @ w_o          fp32 out
    h_gemm<1><<<dim3(DMODEL / 128, ROWS / 128), 256, HG_SMEM>>>(
        ROWS, DMODEL, DMODEL, yh, wo, nullptr, x, x1);
    // 5) ln2 -> fp16
    ln_kernel<<<ROWS, 256>>>(x1, ln2_g, ln2_b, lnh);
    // 6) h = gelu(ln2 @ w_fc + b_fc)   [8192 x 4096] fp16 out
    h_gemm<2><<<dim3(4 * DMODEL / 128, ROWS / 128), 256, HG_SMEM>>>(
        ROWS, 4 * DMODEL, DMODEL, lnh, wf, b_fc, nullptr, hh);
    // 7) out = x1 + h @ w_proj + b_proj   fp32 out
    h_gemm<3><<<dim3(DMODEL / 128, ROWS / 128), 256, HG_SMEM>>>(
        ROWS, DMODEL, 4 * DMODEL, hh, wp, b_proj, x1, out);
}

// round 13
// speedup vs baseline: 1.2912x; 1.0544x over previous
#include <cuda_runtime.h>
#include <cuda_fp16.h>
#include <math.h>
#include <stdint.h>

// ---------------------------------------------------------------------------
// Problem constants
// ---------------------------------------------------------------------------
#define BATCH 4
#define SEQ   2048
#define DMODEL 1024
#define NHEAD 16
#define HDIM  64
#define ROWS  (BATCH * SEQ)          // 8192
#define EPS   1e-5f

// ---------------------------------------------------------------------------
// Scratch buffers (static device globals: allocation-free per harness rules)
// ---------------------------------------------------------------------------
__device__ __half g_lnh[ROWS * DMODEL];       // 16 MB  LN output (fp16, GEMM A)
__device__ __half g_qkv[ROWS * 3 * DMODEL];   // 48 MB  qkv (fp16)
__device__ __half g_yh [ROWS * DMODEL];       // 16 MB  attention out (fp16)
__device__ float  g_x1 [ROWS * DMODEL];       // 32 MB  residual after attn
__device__ __half g_hh [ROWS * 4 * DMODEL];   // 64 MB  MLP hidden (fp16)
// fp16, TRANSPOSED weights [N][K]
__device__ __half g_wa [3 * DMODEL * DMODEL]; // 6 MB
__device__ __half g_wo [DMODEL * DMODEL];     // 2 MB
__device__ __half g_wf [4 * DMODEL * DMODEL]; // 8 MB
__device__ __half g_wp [DMODEL * 4 * DMODEL]; // 8 MB

// ---------------------------------------------------------------------------
// Helpers
// ---------------------------------------------------------------------------
__device__ __forceinline__ uint32_t smem_u32(const void* p) {
    uint32_t a;
    asm("{ .reg .u64 t; cvta.to.shared.u64 t, %1; cvt.u32.u64 %0, t; }"
        : "=r"(a) : "l"(p));
    return a;
}

#define SMEM_SWIZZLE_128B(off) ((off) ^ (((off) >> 3) & 0x70))

__device__ __forceinline__ void ldsm4(unsigned& r0, unsigned& r1,
                                      unsigned& r2, unsigned& r3, uint32_t a) {
    asm volatile("ldmatrix.sync.aligned.m8n8.x4.shared.b16 {%0,%1,%2,%3}, [%4];"
                 : "=r"(r0), "=r"(r1), "=r"(r2), "=r"(r3) : "r"(a));
}

__device__ __forceinline__ void ldsm4_t(unsigned& r0, unsigned& r1,
                                        unsigned& r2, unsigned& r3, uint32_t a) {
    asm volatile("ldmatrix.sync.aligned.m8n8.x4.trans.shared.b16 {%0,%1,%2,%3}, [%4];"
                 : "=r"(r0), "=r"(r1), "=r"(r2), "=r"(r3) : "r"(a));
}

__device__ __forceinline__ void mma_f16(float* c,
                                        unsigned a0, unsigned a1,
                                        unsigned a2, unsigned a3,
                                        unsigned b0, unsigned b1) {
    asm volatile(
        "mma.sync.aligned.m16n8k16.row.col.f32.f16.f16.f32 "
        "{%0,%1,%2,%3}, {%4,%5,%6,%7}, {%8,%9}, {%0,%1,%2,%3};"
        : "+f"(c[0]), "+f"(c[1]), "+f"(c[2]), "+f"(c[3])
        : "r"(a0), "r"(a1), "r"(a2), "r"(a3), "r"(b0), "r"(b1));
}

__device__ __forceinline__ float gelu_tanh(float x) {
    const float c0 = 0.7978845608028654f;  // sqrt(2/pi)
    const float c1 = 0.044715f;
    float t = tanhf(c0 * (x + c1 * x * x * x));
    return 0.5f * x * (1.0f + t);
}

// ---------------------------------------------------------------------------
// Merged transpose+fp16 for ALL FOUR weights in one launch.
// 32x32 tiles, flattened 1D grid of 12288 tiles:
//   [0,3072)     w_attn 1024x3072 -> g_wa   (tN=96)
//   [3072,4096)  w_o    1024x1024 -> g_wo   (tN=32)
//   [4096,8192)  w_fc   1024x4096 -> g_wf   (tN=128)
//   [8192,12288) w_proj 4096x1024 -> g_wp   (tN=32)
// ---------------------------------------------------------------------------
__global__ __launch_bounds__(256) void transpose_all_kernel(
    const float* __restrict__ wa_in, const float* __restrict__ wo_in,
    const float* __restrict__ wf_in, const float* __restrict__ wp_in,
    __half* __restrict__ wa_out, __half* __restrict__ wo_out,
    __half* __restrict__ wf_out, __half* __restrict__ wp_out)
{
    __shared__ float t[32][33];
    const int tile = blockIdx.x;
    const float* in; __half* out; int K, N, local, tN;
    if (tile < 3072)      { in = wa_in; out = wa_out; K = 1024; N = 3072; local = tile;        tN = 96; }
    else if (tile < 4096) { in = wo_in; out = wo_out; K = 1024; N = 1024; local = tile - 3072; tN = 32; }
    else if (tile < 8192) { in = wf_in; out = wf_out; K = 1024; N = 4096; local = tile - 4096; tN = 128; }
    else                  { in = wp_in; out = wp_out; K = 4096; N = 1024; local = tile - 8192; tN = 32; }
    const int n0 = (local % tN) * 32;
    const int k0 = (local / tN) * 32;
    const int tx = threadIdx.x & 31;
    const int ty = threadIdx.x >> 5;   // 0..7

#pragma unroll
    for (int i = 0; i < 4; i++)
        t[ty + 8 * i][tx] = in[(size_t)(k0 + ty + 8 * i) * N + n0 + tx];
    __syncthreads();
#pragma unroll
    for (int i = 0; i < 4; i++)
        out[(size_t)(n0 + ty + 8 * i) * K + k0 + tx] =
            __float2half_rn(t[tx][ty + 8 * i]);
}

// ---------------------------------------------------------------------------
// LayerNorm: fp32 in, fp16 out. 4 rows per block (grid ROWS/4).
// ---------------------------------------------------------------------------
__global__ __launch_bounds__(256) void ln_kernel(
    const float* __restrict__ x,
    const float* __restrict__ g,
    const float* __restrict__ b,
    __half* __restrict__ out)
{
    const int tid = threadIdx.x;
    const int wid = tid >> 5, lane = tid & 31;
    const float4 gv = reinterpret_cast<const float4*>(g)[tid];
    const float4 bv = reinterpret_cast<const float4*>(b)[tid];
    __shared__ float red0[8], red1[8];

#pragma unroll
    for (int rr = 0; rr < 4; rr++) {
        const int row = blockIdx.x * 4 + rr;
        const float4 v = reinterpret_cast<const float4*>(
            x + (size_t)row * DMODEL)[tid];

        float s  = v.x + v.y + v.z + v.w;
        float ss = v.x*v.x + v.y*v.y + v.z*v.z + v.w*v.w;
#pragma unroll
        for (int o = 16; o > 0; o >>= 1) {
            s  += __shfl_xor_sync(0xffffffffu, s, o);
            ss += __shfl_xor_sync(0xffffffffu, ss, o);
        }
        if (lane == 0) { red0[wid] = s; red1[wid] = ss; }
        __syncthreads();
        float ts = 0.f, tss = 0.f;
#pragma unroll
        for (int w = 0; w < 8; w++) { ts += red0[w]; tss += red1[w]; }

        const float mean = ts * (1.0f / DMODEL);
        const float var  = tss * (1.0f / DMODEL) - mean * mean;
        const float rstd = rsqrtf(var + EPS);

        __half2 h0 = __floats2half2_rn((v.x - mean) * rstd * gv.x + bv.x,
                                       (v.y - mean) * rstd * gv.y + bv.y);
        __half2 h1 = __floats2half2_rn((v.z - mean) * rstd * gv.z + bv.z,
                                       (v.w - mean) * rstd * gv.w + bv.w);
        __half2* op = reinterpret_cast<__half2*>(out + (size_t)row * DMODEL);
        op[tid * 2 + 0] = h0;
        op[tid * 2 + 1] = h1;
        __syncthreads();   // red[] reuse next row
    }
}

// ---------------------------------------------------------------------------
// FP16 tensor-core GEMM (128x128, BK=64, 3-stage, 2 CTAs/SM, single sync)
// EPI: 0 none(f32) | 1 +res(f32) | 2 gelu(acc+bias)->fp16 | 3 +bias+res(f32)
//      4 plain fp16 out
// ---------------------------------------------------------------------------
#define HG_TILE 16384                        // 128 rows x 128 bytes
#define HG_A_OFF(s) ((s) * 2 * HG_TILE)
#define HG_B_OFF(s) ((s) * 2 * HG_TILE + HG_TILE)
#define HG_SMEM (3 * 2 * HG_TILE)            // 98304 B

__device__ __forceinline__ void hg_load_chunk(
    uint32_t smem_base, int stage,
    const __half* __restrict__ Ag, const __half* __restrict__ Bg,
    int K, int c, int tid)
{
    const int kk = c * 64;
#pragma unroll
    for (int i = 0; i < 4; i++) {
        const int L = tid + i * 256;          // 0..1023
        const int row = L >> 3;
        const int unit = L & 7;
        const uint32_t sw = SMEM_SWIZZLE_128B((uint32_t)(row * 128 + unit * 16));
        const __half* ap = Ag + (size_t)row * K + kk + unit * 8;
        const __half* bp = Bg + (size_t)row * K + kk + unit * 8;
        asm volatile("cp.async.cg.shared.global [%0], [%1], 16;"
                     :: "r"(smem_base + HG_A_OFF(stage) + sw), "l"(ap));
        asm volatile("cp.async.cg.shared.global [%0], [%1], 16;"
                     :: "r"(smem_base + HG_B_OFF(stage) + sw), "l"(bp));
    }
    asm volatile("cp.async.commit_group;");
}

template <int EPI>
__global__ __launch_bounds__(256, 2) void h_gemm(
    int M, int N, int K,
    const __half* __restrict__ A,
    const __half* __restrict__ Bt,
    const float* __restrict__ bias,
    const float* __restrict__ res,
    void* __restrict__ Cv)
{
    extern __shared__ char smem[];
    const uint32_t smem_base = smem_u32(smem);

    const int tid  = threadIdx.x;
    const int lane = tid & 31;
    const int wid  = tid >> 5;
    const int m_w  = (wid >> 2) * 64;   // warp M origin (0 or 64)
    const int n_w  = (wid & 3) * 32;    // warp N origin

    const __half* Ag = A  + (size_t)(blockIdx.y * 128) * K;
    const __half* Bg = Bt + (size_t)(blockIdx.x * 128) * K;

    float acc[4][4][4];
#pragma unroll
    for (int i = 0; i < 4; i++)
#pragma unroll
        for (int j = 0; j < 4; j++)
#pragma unroll
            for (int q = 0; q < 4; q++) acc[i][j][q] = 0.f;

    const int lr  = lane & 7;
    const int lm8 = ((lane >> 3) & 1) * 8;
    const int ub  = lane >> 4;                 // 16B unit select (0/1)
    const int rowA = m_w + lr + lm8;           // + mf*16
    const int rowB = n_w + lr + lm8;           // + nt*16

    const int nk = K >> 6;

    hg_load_chunk(smem_base, 0, Ag, Bg, K, 0, tid);
    hg_load_chunk(smem_base, 1, Ag, Bg, K, 1, tid);

    int st = 0, ld = 2;
    for (int c = 0; c < nk; c++) {
        if (c + 1 < nk) {
            asm volatile("cp.async.wait_group 1;");
        } else {
            asm volatile("cp.async.wait_group 0;");
        }
        __syncthreads();
        if (c + 2 < nk) {
            hg_load_chunk(smem_base, ld, Ag, Bg, K, c + 2, tid);
        }

        const uint32_t aT = smem_base + HG_A_OFF(st);
        const uint32_t bT = smem_base + HG_B_OFF(st);

#pragma unroll
        for (int ks = 0; ks < 4; ks++) {
            const int u = ks * 2 + ub;
            unsigned av[4][4];
#pragma unroll
            for (int mf = 0; mf < 4; mf++) {
                const uint32_t off = (uint32_t)((rowA + mf * 16) * 128 + u * 16);
                ldsm4(av[mf][0], av[mf][1], av[mf][2], av[mf][3],
                      aT + SMEM_SWIZZLE_128B(off));
            }
            unsigned bv[2][4];
#pragma unroll
            for (int nt = 0; nt < 2; nt++) {
                const uint32_t off = (uint32_t)((rowB + nt * 16) * 128 + u * 16);
                ldsm4(bv[nt][0], bv[nt][1], bv[nt][2], bv[nt][3],
                      bT + SMEM_SWIZZLE_128B(off));
            }
#pragma unroll
            for (int mf = 0; mf < 4; mf++)
#pragma unroll
                for (int nt = 0; nt < 2; nt++) {
                    mma_f16(acc[mf][nt * 2 + 0],
                            av[mf][0], av[mf][1], av[mf][2], av[mf][3],
                            bv[nt][0], bv[nt][2]);
                    mma_f16(acc[mf][nt * 2 + 1],
                            av[mf][0], av[mf][1], av[mf][2], av[mf][3],
                            bv[nt][1], bv[nt][3]);
                }
        }
        st++; if (st == 3) st = 0;
        ld++; if (ld == 3) ld = 0;
    }

    // ---------------- epilogue (no smem use -> no final barrier) ----------
    float*  Cf = (float*)Cv;
    __half* Ch = (__half*)Cv;
    const int row0 = blockIdx.y * 128 + m_w;
    const int col0 = blockIdx.x * 128 + n_w;

#pragma unroll
    for (int mf = 0; mf < 4; mf++) {
#pragma unroll
        for (int nf = 0; nf < 4; nf++) {
            const int r = row0 + mf * 16 + (lane >> 2);
            const int c = col0 + nf * 8 + (lane & 3) * 2;
            float b0 = 0.f, b1 = 0.f;
            if (EPI == 2 || EPI == 3) { b0 = bias[c]; b1 = bias[c + 1]; }
#pragma unroll
            for (int half = 0; half < 2; half++) {
                const int rr = r + half * 8;
                float v0 = acc[mf][nf][half * 2 + 0];
                float v1 = acc[mf][nf][half * 2 + 1];
                if (EPI == 2) {
                    v0 = gelu_tanh(v0 + b0);
                    v1 = gelu_tanh(v1 + b1);
                    *reinterpret_cast<__half2*>(Ch + (size_t)rr * N + c) =
                        __floats2half2_rn(v0, v1);
                } else if (EPI == 4) {
                    *reinterpret_cast<__half2*>(Ch + (size_t)rr * N + c) =
                        __floats2half2_rn(v0, v1);
                } else {
                    if (EPI == 3) { v0 += b0; v1 += b1; }
                    if (EPI == 1 || EPI == 3) {
                        const float2 rv = *reinterpret_cast<const float2*>(
                            res + (size_t)rr * N + c);
                        v0 += rv.x; v1 += rv.y;
                    }
                    float2 o; o.x = v0; o.y = v1;
                    *reinterpret_cast<float2*>(Cf + (size_t)rr * N + c) = o;
                }
            }
        }
    }
}

// ---------------------------------------------------------------------------
// Full-fp16 tensor-core causal flash attention with DOUBLE-BUFFERED K/V
// (cp.async prefetch of tile kt+1 overlaps compute of kt).
// Grid: (qtile 0..15, b*H 0..63). 256 threads = 8 warps; warp w owns q rows
// [16w, 16w+16). Tiles 128B/row SW128 (validated h_gemm addressing):
//   Q [128][64]h @0, K[2] 8KB @16K/24K, V[2] 8KB @32K/40K, P [128][64]h @48K
// ---------------------------------------------------------------------------
#define AQ_OFF 0
#define AK_OFF(buf) (16384 + (buf) * 8192)
#define AV_OFF(buf) (32768 + (buf) * 8192)
#define AP_OFF 49152
#define ATTH_SMEM 65536

__device__ __forceinline__ void att_kv_load(
    uint32_t sb, int buf,
    const __half* __restrict__ kb, const __half* __restrict__ vb,
    int kt, int tid)
{
    const size_t rstr = 3 * DMODEL;
#pragma unroll
    for (int i = 0; i < 2; i++) {
        const int L = tid + i * 256;   // 0..511
        const int row = L >> 3, unit = L & 7;
        const size_t src = (size_t)(kt * 64 + row) * rstr + unit * 8;
        const uint32_t sw = SMEM_SWIZZLE_128B((uint32_t)(row * 128 + unit * 16));
        asm volatile("cp.async.cg.shared.global [%0], [%1], 16;"
                     :: "r"(sb + AK_OFF(buf) + sw), "l"(kb + src));
        asm volatile("cp.async.cg.shared.global [%0], [%1], 16;"
                     :: "r"(sb + AV_OFF(buf) + sw), "l"(vb + src));
    }
    asm volatile("cp.async.commit_group;");
}

__global__ __launch_bounds__(256) void attn_h_kernel(
    const __half* __restrict__ qkv,
    __half* __restrict__ y)
{
    extern __shared__ char smc[];
    const uint32_t sb = smem_u32(smc);

    const int qt  = blockIdx.x;
    const int bh  = blockIdx.y;
    const int b   = bh >> 4;
    const int h   = bh & 15;
    const int tid = threadIdx.x;
    const int lane = tid & 31;
    const int wid  = tid >> 5;

    const size_t rstr = 3 * DMODEL;   // halves
    const __half* qb = qkv + ((size_t)b * SEQ + qt * 128) * rstr + h * HDIM;
    const __half* kb = qkv + (size_t)b * SEQ * rstr + DMODEL     + h * HDIM;
    const __half* vb = qkv + (size_t)b * SEQ * rstr + 2 * DMODEL + h * HDIM;

    // preload K/V tile 0 (overlaps with the Q load below)
    att_kv_load(sb, 0, kb, vb, 0, tid);

    // load Q tile, scaled by 1/sqrt(64) = 0.125 (exact in fp16)
    const __half2 qsc = __float2half2_rn(0.125f);
#pragma unroll
    for (int i = 0; i < 4; i++) {
        const int L = tid + i * 256;       // 0..1023
        const int row = L >> 3, unit = L & 7;
        uint4 t = *reinterpret_cast<const uint4*>(qb + (size_t)row * rstr + unit * 8);
        __half2* tp = reinterpret_cast<__half2*>(&t);
#pragma unroll
        for (int j = 0; j < 4; j++) tp[j] = __hmul2(tp[j], qsc);
        *reinterpret_cast<uint4*>(smc + AQ_OFF +
            SMEM_SWIZZLE_128B((uint32_t)(row * 128 + unit * 16))) = t;
    }

    float m0 = -1e30f, m1 = -1e30f, l0 = 0.f, l1 = 0.f;
    float acc[8][4];
#pragma unroll
    for (int nf = 0; nf < 8; nf++)
#pragma unroll
        for (int q = 0; q < 4; q++) acc[nf][q] = 0.f;

    const int lr  = lane & 7;
    const int lm8 = ((lane >> 3) & 1) * 8;
    const int ub  = lane >> 4;
    const int q0w = qt * 128 + wid * 16;
    const int nkv = 2 * qt + 2;

    for (int kt = 0; kt < nkv; kt++) {
        asm volatile("cp.async.wait_group 0;");   // K/V tile kt arrived
        __syncthreads();                          // all warps past compute(kt-1)
        if (kt + 1 < nkv)
            att_kv_load(sb, (kt + 1) & 1, kb, vb, kt + 1, tid);

        const uint32_t kT = sb + AK_OFF(kt & 1);
        const uint32_t vT = sb + AV_OFF(kt & 1);

        if (kt * 64 <= q0w + 15) {   // warp not fully masked
            // ---- S = Q @ K^T (warp tile 16 x 64) ----
            float s[8][4];
#pragma unroll
            for (int nf = 0; nf < 8; nf++)
#pragma unroll
                for (int q = 0; q < 4; q++) s[nf][q] = 0.f;

#pragma unroll
            for (int ks = 0; ks < 4; ks++) {
                const int u = ks * 2 + ub;
                unsigned a0, a1, a2, a3;
                ldsm4(a0, a1, a2, a3, sb + AQ_OFF + SMEM_SWIZZLE_128B(
                    (uint32_t)((wid * 16 + lr + lm8) * 128 + u * 16)));
#pragma unroll
                for (int nt = 0; nt < 4; nt++) {
                    unsigned b0, b1, b2, b3;
                    ldsm4(b0, b1, b2, b3, kT + SMEM_SWIZZLE_128B(
                        (uint32_t)((nt * 16 + lr + lm8) * 128 + u * 16)));
                    mma_f16(s[nt * 2 + 0], a0, a1, a2, a3, b0, b2);
                    mma_f16(s[nt * 2 + 1], a0, a1, a2, a3, b1, b3);
                }
            }

            // ---- causal mask (diagonal tiles only) ----
            if (kt >= 2 * qt) {
                const int r_lo = q0w + (lane >> 2);
#pragma unroll
                for (int nf = 0; nf < 8; nf++) {
                    int kg = kt * 64 + nf * 8 + 2 * (lane & 3);
                    if (kg     > r_lo)     s[nf][0] = -1e30f;
                    if (kg + 1 > r_lo)     s[nf][1] = -1e30f;
                    if (kg     > r_lo + 8) s[nf][2] = -1e30f;
                    if (kg + 1 > r_lo + 8) s[nf][3] = -1e30f;
                }
            }

            // ---- online softmax (rows lane>>2 and +8; quad shfl reduce) ----
            float mx0 = -1e30f, mx1 = -1e30f;
#pragma unroll
            for (int nf = 0; nf < 8; nf++) {
                mx0 = fmaxf(mx0, fmaxf(s[nf][0], s[nf][1]));
                mx1 = fmaxf(mx1, fmaxf(s[nf][2], s[nf][3]));
            }
            mx0 = fmaxf(mx0, __shfl_xor_sync(0xffffffffu, mx0, 1));
            mx0 = fmaxf(mx0, __shfl_xor_sync(0xffffffffu, mx0, 2));
            mx1 = fmaxf(mx1, __shfl_xor_sync(0xffffffffu, mx1, 1));
            mx1 = fmaxf(mx1, __shfl_xor_sync(0xffffffffu, mx1, 2));

            const float mn0 = fmaxf(m0, mx0);
            const float mn1 = fmaxf(m1, mx1);
            const float cor0 = __expf(m0 - mn0);
            const float cor1 = __expf(m1 - mn1);
            float sum0 = 0.f, sum1 = 0.f;
            const uint32_t pr0 = (uint32_t)((wid * 16 + (lane >> 2)) * 128
                                            + (lane & 3) * 4);
#pragma unroll
            for (int nf = 0; nf < 8; nf++) {
                float p0 = __expf(s[nf][0] - mn0);
                float p1 = __expf(s[nf][1] - mn0);
                float p2 = __expf(s[nf][2] - mn1);
                float p3 = __expf(s[nf][3] - mn1);
                sum0 += p0 + p1;
                sum1 += p2 + p3;
                *reinterpret_cast<__half2*>(smc + AP_OFF +
                    SMEM_SWIZZLE_128B(pr0 + (uint32_t)(nf * 16))) =
                    __floats2half2_rn(p0, p1);
                *reinterpret_cast<__half2*>(smc + AP_OFF +
                    SMEM_SWIZZLE_128B(pr0 + 8 * 128 + (uint32_t)(nf * 16))) =
                    __floats2half2_rn(p2, p3);
            }
            sum0 += __shfl_xor_sync(0xffffffffu, sum0, 1);
            sum0 += __shfl_xor_sync(0xffffffffu, sum0, 2);
            sum1 += __shfl_xor_sync(0xffffffffu, sum1, 1);
            sum1 += __shfl_xor_sync(0xffffffffu, sum1, 2);

            l0 = l0 * cor0 + sum0;
            l1 = l1 * cor1 + sum1;
            m0 = mn0; m1 = mn1;
#pragma unroll
            for (int nf = 0; nf < 8; nf++) {
                acc[nf][0] *= cor0; acc[nf][1] *= cor0;
                acc[nf][2] *= cor1; acc[nf][3] *= cor1;
            }
            __syncwarp();   // Ps visible to ldmatrix across lanes

            // ---- O += P @ V  (V via ldmatrix.trans) ----
#pragma unroll
            for (int ks = 0; ks < 4; ks++) {
                unsigned p0, p1, p2, p3;
                ldsm4(p0, p1, p2, p3, sb + AP_OFF + SMEM_SWIZZLE_128B(
                    (uint32_t)((wid * 16 + lr + lm8) * 128
                               + (ks * 2 + ub) * 16)));
#pragma unroll
                for (int nt = 0; nt < 4; nt++) {
                    unsigned v0, v1, v2, v3;
                    ldsm4_t(v0, v1, v2, v3, vT + SMEM_SWIZZLE_128B(
                        (uint32_t)((ks * 16 + lr + lm8) * 128
                                   + (nt * 2 + ub) * 16)));
                    mma_f16(acc[nt * 2 + 0], p0, p1, p2, p3, v0, v1);
                    mma_f16(acc[nt * 2 + 1], p0, p1, p2, p3, v2, v3);
                }
            }
            __syncwarp();   // PV reads done before next iter's Ps writes
        }
    }

    // ---- normalize + write fp16 ----
    const float inv0 = 1.0f / l0;
    const float inv1 = 1.0f / l1;
    const size_t row_lo = (size_t)b * SEQ + qt * 128 + wid * 16 + (lane >> 2);
#pragma unroll
    for (int nf = 0; nf < 8; nf++) {
        const int col = h * HDIM + nf * 8 + 2 * (lane & 3);
        *reinterpret_cast<__half2*>(&y[row_lo * DMODEL + col]) =
            __floats2half2_rn(acc[nf][0] * inv0, acc[nf][1] * inv0);
        *reinterpret_cast<__half2*>(&y[(row_lo + 8) * DMODEL + col]) =
            __floats2half2_rn(acc[nf][2] * inv1, acc[nf][3] * inv1);
    }
}

// ---------------------------------------------------------------------------
// Launch
// ---------------------------------------------------------------------------
extern "C" void kernel_launch(void* const* d_in, const int* in_sizes, int n_in,
                              void* d_out, int out_size)
{
    const float* x      = (const float*)d_in[0];
    const float* w_attn = (const float*)d_in[1];
    const float* w_o    = (const float*)d_in[2];
    const float* ln1_g  = (const float*)d_in[3];
    const float* ln1_b  = (const float*)d_in[4];
    const float* ln2_g  = (const float*)d_in[5];
    const float* ln2_b  = (const float*)d_in[6];
    const float* w_fc   = (const float*)d_in[7];
    const float* b_fc   = (const float*)d_in[8];
    const float* w_proj = (const float*)d_in[9];
    const float* b_proj = (const float*)d_in[10];
    float* out = (float*)d_out;

    __half *lnh, *qkvp, *yh, *hh, *wa, *wo, *wf, *wp;
    float *x1;
    cudaGetSymbolAddress((void**)&lnh,  g_lnh);
    cudaGetSymbolAddress((void**)&qkvp, g_qkv);
    cudaGetSymbolAddress((void**)&yh,   g_yh);
    cudaGetSymbolAddress((void**)&x1,   g_x1);
    cudaGetSymbolAddress((void**)&hh,   g_hh);
    cudaGetSymbolAddress((void**)&wa,   g_wa);
    cudaGetSymbolAddress((void**)&wo,   g_wo);
    cudaGetSymbolAddress((void**)&wf,   g_wf);
    cudaGetSymbolAddress((void**)&wp,   g_wp);

    cudaFuncSetAttribute(attn_h_kernel,
                         cudaFuncAttributeMaxDynamicSharedMemorySize, ATTH_SMEM);
    cudaFuncSetAttribute(h_gemm<1>,
                         cudaFuncAttributeMaxDynamicSharedMemorySize, HG_SMEM);
    cudaFuncSetAttribute(h_gemm<2>,
                         cudaFuncAttributeMaxDynamicSharedMemorySize, HG_SMEM);
    cudaFuncSetAttribute(h_gemm<3>,
                         cudaFuncAttributeMaxDynamicSharedMemorySize, HG_SMEM);
    cudaFuncSetAttribute(h_gemm<4>,
                         cudaFuncAttributeMaxDynamicSharedMemorySize, HG_SMEM);

    // 0) transpose + fp16-convert all weights (single launch)
    transpose_all_kernel<<<12288, 256>>>(
        w_attn, w_o, w_fc, w_proj, wa, wo, wf, wp);

    // 1) ln1 -> fp16
    ln_kernel<<<ROWS / 4, 256>>>(x, ln1_g, ln1_b, lnh);
    // 2) qkv = ln1 @ w_attn        [8192 x 3072] fp16 out
    h_gemm<4><<<dim3(3 * DMODEL / 128, ROWS / 128), 256, HG_SMEM>>>(
        ROWS, 3 * DMODEL, DMODEL, lnh, wa, nullptr, nullptr, qkvp);
    // 3) attention -> y (fp16, double-buffered KV)
    attn_h_kernel<<<dim3(SEQ / 128, BATCH * NHEAD), 256, ATTH_SMEM>>>(qkvp, yh);
    // 4) x1 = x + y @ w_o          fp32 out
    h_gemm<1><<<dim3(DMODEL / 128, ROWS / 128), 256, HG_SMEM>>>(
        ROWS, DMODEL, DMODEL, yh, wo, nullptr, x, x1);
    // 5) ln2 -> fp16
    ln_kernel<<<ROWS / 4, 256>>>(x1, ln2_g, ln2_b, lnh);
    // 6) h = gelu(ln2 @ w_fc + b_fc)   [8192 x 4096] fp16 out
    h_gemm<2><<<dim3(4 * DMODEL / 128, ROWS / 128), 256, HG_SMEM>>>(
        ROWS, 4 * DMODEL, DMODEL, lnh, wf, b_fc, nullptr, hh);
    // 7) out = x1 + h @ w_proj + b_proj   fp32 out
    h_gemm<3><<<dim3(DMODEL / 128, ROWS / 128), 256, HG_SMEM>>>(
        ROWS, DMODEL, 4 * DMODEL, hh, wp, b_proj, x1, out);
}

// round 15
// speedup vs baseline: 1.3209x; 1.0229x over previous
#include <cuda_runtime.h>
#include <cuda_fp16.h>
#include <math.h>
#include <stdint.h>

// ---------------------------------------------------------------------------
// Problem constants
// ---------------------------------------------------------------------------
#define BATCH 4
#define SEQ   2048
#define DMODEL 1024
#define NHEAD 16
#define HDIM  64
#define ROWS  (BATCH * SEQ)          // 8192
#define EPS   1e-5f

// ---------------------------------------------------------------------------
// Scratch buffers (static device globals: allocation-free per harness rules)
// ---------------------------------------------------------------------------
__device__ __half g_lnh[ROWS * DMODEL];       // 16 MB  LN output (fp16, GEMM A)
__device__ __half g_qkv[ROWS * 3 * DMODEL];   // 48 MB  qkv (fp16)
__device__ __half g_yh [ROWS * DMODEL];       // 16 MB  attention out (fp16)
__device__ float  g_x1 [ROWS * DMODEL];       // 32 MB  residual after attn
__device__ __half g_hh [ROWS * 4 * DMODEL];   // 64 MB  MLP hidden (fp16)
// fp16, TRANSPOSED weights [N][K]
__device__ __half g_wa [3 * DMODEL * DMODEL]; // 6 MB
__device__ __half g_wo [DMODEL * DMODEL];     // 2 MB
__device__ __half g_wf [4 * DMODEL * DMODEL]; // 8 MB
__device__ __half g_wp [DMODEL * 4 * DMODEL]; // 8 MB

// ---------------------------------------------------------------------------
// Helpers
// ---------------------------------------------------------------------------
__device__ __forceinline__ uint32_t smem_u32(const void* p) {
    uint32_t a;
    asm("{ .reg .u64 t; cvta.to.shared.u64 t, %1; cvt.u32.u64 %0, t; }"
        : "=r"(a) : "l"(p));
    return a;
}

#define SMEM_SWIZZLE_128B(off) ((off) ^ (((off) >> 3) & 0x70))

__device__ __forceinline__ void ldsm4(unsigned& r0, unsigned& r1,
                                      unsigned& r2, unsigned& r3, uint32_t a) {
    asm volatile("ldmatrix.sync.aligned.m8n8.x4.shared.b16 {%0,%1,%2,%3}, [%4];"
                 : "=r"(r0), "=r"(r1), "=r"(r2), "=r"(r3) : "r"(a));
}

__device__ __forceinline__ void ldsm4_t(unsigned& r0, unsigned& r1,
                                        unsigned& r2, unsigned& r3, uint32_t a) {
    asm volatile("ldmatrix.sync.aligned.m8n8.x4.trans.shared.b16 {%0,%1,%2,%3}, [%4];"
                 : "=r"(r0), "=r"(r1), "=r"(r2), "=r"(r3) : "r"(a));
}

__device__ __forceinline__ void mma_f16(float* c,
                                        unsigned a0, unsigned a1,
                                        unsigned a2, unsigned a3,
                                        unsigned b0, unsigned b1) {
    asm volatile(
        "mma.sync.aligned.m16n8k16.row.col.f32.f16.f16.f32 "
        "{%0,%1,%2,%3}, {%4,%5,%6,%7}, {%8,%9}, {%0,%1,%2,%3};"
        : "+f"(c[0]), "+f"(c[1]), "+f"(c[2]), "+f"(c[3])
        : "r"(a0), "r"(a1), "r"(a2), "r"(a3), "r"(b0), "r"(b1));
}

__device__ __forceinline__ float gelu_tanh(float x) {
    const float c0 = 0.7978845608028654f;  // sqrt(2/pi)
    const float c1 = 0.044715f;
    float t = tanhf(c0 * (x + c1 * x * x * x));
    return 0.5f * x * (1.0f + t);
}

// ---------------------------------------------------------------------------
// Merged transpose+fp16 for ALL FOUR weights in one launch.
// 32x32 tiles, flattened 1D grid of 12288 tiles.
// ---------------------------------------------------------------------------
__global__ __launch_bounds__(256) void transpose_all_kernel(
    const float* __restrict__ wa_in, const float* __restrict__ wo_in,
    const float* __restrict__ wf_in, const float* __restrict__ wp_in,
    __half* __restrict__ wa_out, __half* __restrict__ wo_out,
    __half* __restrict__ wf_out, __half* __restrict__ wp_out)
{
    __shared__ float t[32][33];
    const int tile = blockIdx.x;
    const float* in; __half* out; int K, N, local, tN;
    if (tile < 3072)      { in = wa_in; out = wa_out; K = 1024; N = 3072; local = tile;        tN = 96; }
    else if (tile < 4096) { in = wo_in; out = wo_out; K = 1024; N = 1024; local = tile - 3072; tN = 32; }
    else if (tile < 8192) { in = wf_in; out = wf_out; K = 1024; N = 4096; local = tile - 4096; tN = 128; }
    else                  { in = wp_in; out = wp_out; K = 4096; N = 1024; local = tile - 8192; tN = 32; }
    const int n0 = (local % tN) * 32;
    const int k0 = (local / tN) * 32;
    const int tx = threadIdx.x & 31;
    const int ty = threadIdx.x >> 5;   // 0..7

#pragma unroll
    for (int i = 0; i < 4; i++)
        t[ty + 8 * i][tx] = in[(size_t)(k0 + ty + 8 * i) * N + n0 + tx];
    __syncthreads();
#pragma unroll
    for (int i = 0; i < 4; i++)
        out[(size_t)(n0 + ty + 8 * i) * K + k0 + tx] =
            __float2half_rn(t[tx][ty + 8 * i]);
}

// ---------------------------------------------------------------------------
// LayerNorm: fp32 in, fp16 out. 4 rows per block (grid ROWS/4).
// ---------------------------------------------------------------------------
__global__ __launch_bounds__(256) void ln_kernel(
    const float* __restrict__ x,
    const float* __restrict__ g,
    const float* __restrict__ b,
    __half* __restrict__ out)
{
    const int tid = threadIdx.x;
    const int wid = tid >> 5, lane = tid & 31;
    const float4 gv = reinterpret_cast<const float4*>(g)[tid];
    const float4 bv = reinterpret_cast<const float4*>(b)[tid];
    __shared__ float red0[8], red1[8];

#pragma unroll
    for (int rr = 0; rr < 4; rr++) {
        const int row = blockIdx.x * 4 + rr;
        const float4 v = reinterpret_cast<const float4*>(
            x + (size_t)row * DMODEL)[tid];

        float s  = v.x + v.y + v.z + v.w;
        float ss = v.x*v.x + v.y*v.y + v.z*v.z + v.w*v.w;
#pragma unroll
        for (int o = 16; o > 0; o >>= 1) {
            s  += __shfl_xor_sync(0xffffffffu, s, o);
            ss += __shfl_xor_sync(0xffffffffu, ss, o);
        }
        if (lane == 0) { red0[wid] = s; red1[wid] = ss; }
        __syncthreads();
        float ts = 0.f, tss = 0.f;
#pragma unroll
        for (int w = 0; w < 8; w++) { ts += red0[w]; tss += red1[w]; }

        const float mean = ts * (1.0f / DMODEL);
        const float var  = tss * (1.0f / DMODEL) - mean * mean;
        const float rstd = rsqrtf(var + EPS);

        __half2 h0 = __floats2half2_rn((v.x - mean) * rstd * gv.x + bv.x,
                                       (v.y - mean) * rstd * gv.y + bv.y);
        __half2 h1 = __floats2half2_rn((v.z - mean) * rstd * gv.z + bv.z,
                                       (v.w - mean) * rstd * gv.w + bv.w);
        __half2* op = reinterpret_cast<__half2*>(out + (size_t)row * DMODEL);
        op[tid * 2 + 0] = h0;
        op[tid * 2 + 1] = h1;
        __syncthreads();   // red[] reuse next row
    }
}

// ---------------------------------------------------------------------------
// FP16 tensor-core GEMM (128x128, BK=64, 3-stage, 2 CTAs/SM, single sync)
// EPI: 0 none(f32) | 1 +res(f32) | 2 gelu(acc+bias)->fp16 | 3 +bias+res(f32)
//      4 plain fp16 out
// ---------------------------------------------------------------------------
#define HG_TILE 16384                        // 128 rows x 128 bytes
#define HG_A_OFF(s) ((s) * 2 * HG_TILE)
#define HG_B_OFF(s) ((s) * 2 * HG_TILE + HG_TILE)
#define HG_SMEM (3 * 2 * HG_TILE)            // 98304 B

__device__ __forceinline__ void hg_load_chunk(
    uint32_t smem_base, int stage,
    const __half* __restrict__ Ag, const __half* __restrict__ Bg,
    int K, int c, int tid)
{
    const int kk = c * 64;
#pragma unroll
    for (int i = 0; i < 4; i++) {
        const int L = tid + i * 256;          // 0..1023
        const int row = L >> 3;
        const int unit = L & 7;
        const uint32_t sw = SMEM_SWIZZLE_128B((uint32_t)(row * 128 + unit * 16));
        const __half* ap = Ag + (size_t)row * K + kk + unit * 8;
        const __half* bp = Bg + (size_t)row * K + kk + unit * 8;
        asm volatile("cp.async.cg.shared.global [%0], [%1], 16;"
                     :: "r"(smem_base + HG_A_OFF(stage) + sw), "l"(ap));
        asm volatile("cp.async.cg.shared.global [%0], [%1], 16;"
                     :: "r"(smem_base + HG_B_OFF(stage) + sw), "l"(bp));
    }
    asm volatile("cp.async.commit_group;");
}

template <int EPI>
__global__ __launch_bounds__(256, 2) void h_gemm(
    int M, int N, int K,
    const __half* __restrict__ A,
    const __half* __restrict__ Bt,
    const float* __restrict__ bias,
    const float* __restrict__ res,
    void* __restrict__ Cv)
{
    extern __shared__ char smem[];
    const uint32_t smem_base = smem_u32(smem);

    const int tid  = threadIdx.x;
    const int lane = tid & 31;
    const int wid  = tid >> 5;
    const int m_w  = (wid >> 2) * 64;   // warp M origin (0 or 64)
    const int n_w  = (wid & 3) * 32;    // warp N origin

    const __half* Ag = A  + (size_t)(blockIdx.y * 128) * K;
    const __half* Bg = Bt + (size_t)(blockIdx.x * 128) * K;

    float acc[4][4][4];
#pragma unroll
    for (int i = 0; i < 4; i++)
#pragma unroll
        for (int j = 0; j < 4; j++)
#pragma unroll
            for (int q = 0; q < 4; q++) acc[i][j][q] = 0.f;

    const int lr  = lane & 7;
    const int lm8 = ((lane >> 3) & 1) * 8;
    const int ub  = lane >> 4;                 // 16B unit select (0/1)
    const int rowA = m_w + lr + lm8;           // + mf*16
    const int rowB = n_w + lr + lm8;           // + nt*16

    const int nk = K >> 6;

    hg_load_chunk(smem_base, 0, Ag, Bg, K, 0, tid);
    hg_load_chunk(smem_base, 1, Ag, Bg, K, 1, tid);

    int st = 0, ld = 2;
    for (int c = 0; c < nk; c++) {
        if (c + 1 < nk) {
            asm volatile("cp.async.wait_group 1;");
        } else {
            asm volatile("cp.async.wait_group 0;");
        }
        __syncthreads();
        if (c + 2 < nk) {
            hg_load_chunk(smem_base, ld, Ag, Bg, K, c + 2, tid);
        }

        const uint32_t aT = smem_base + HG_A_OFF(st);
        const uint32_t bT = smem_base + HG_B_OFF(st);

#pragma unroll
        for (int ks = 0; ks < 4; ks++) {
            const int u = ks * 2 + ub;
            unsigned av[4][4];
#pragma unroll
            for (int mf = 0; mf < 4; mf++) {
                const uint32_t off = (uint32_t)((rowA + mf * 16) * 128 + u * 16);
                ldsm4(av[mf][0], av[mf][1], av[mf][2], av[mf][3],
                      aT + SMEM_SWIZZLE_128B(off));
            }
            unsigned bv[2][4];
#pragma unroll
            for (int nt = 0; nt < 2; nt++) {
                const uint32_t off = (uint32_t)((rowB + nt * 16) * 128 + u * 16);
                ldsm4(bv[nt][0], bv[nt][1], bv[nt][2], bv[nt][3],
                      bT + SMEM_SWIZZLE_128B(off));
            }
#pragma unroll
            for (int mf = 0; mf < 4; mf++)
#pragma unroll
                for (int nt = 0; nt < 2; nt++) {
                    mma_f16(acc[mf][nt * 2 + 0],
                            av[mf][0], av[mf][1], av[mf][2], av[mf][3],
                            bv[nt][0], bv[nt][2]);
                    mma_f16(acc[mf][nt * 2 + 1],
                            av[mf][0], av[mf][1], av[mf][2], av[mf][3],
                            bv[nt][1], bv[nt][3]);
                }
        }
        st++; if (st == 3) st = 0;
        ld++; if (ld == 3) ld = 0;
    }

    // ---------------- epilogue (no smem use -> no final barrier) ----------
    float*  Cf = (float*)Cv;
    __half* Ch = (__half*)Cv;
    const int row0 = blockIdx.y * 128 + m_w;
    const int col0 = blockIdx.x * 128 + n_w;

#pragma unroll
    for (int mf = 0; mf < 4; mf++) {
#pragma unroll
        for (int nf = 0; nf < 4; nf++) {
            const int r = row0 + mf * 16 + (lane >> 2);
            const int c = col0 + nf * 8 + (lane & 3) * 2;
            float b0 = 0.f, b1 = 0.f;
            if (EPI == 2 || EPI == 3) { b0 = bias[c]; b1 = bias[c + 1]; }
#pragma unroll
            for (int half = 0; half < 2; half++) {
                const int rr = r + half * 8;
                float v0 = acc[mf][nf][half * 2 + 0];
                float v1 = acc[mf][nf][half * 2 + 1];
                if (EPI == 2) {
                    v0 = gelu_tanh(v0 + b0);
                    v1 = gelu_tanh(v1 + b1);
                    *reinterpret_cast<__half2*>(Ch + (size_t)rr * N + c) =
                        __floats2half2_rn(v0, v1);
                } else if (EPI == 4) {
                    *reinterpret_cast<__half2*>(Ch + (size_t)rr * N + c) =
                        __floats2half2_rn(v0, v1);
                } else {
                    if (EPI == 3) { v0 += b0; v1 += b1; }
                    if (EPI == 1 || EPI == 3) {
                        const float2 rv = *reinterpret_cast<const float2*>(
                            res + (size_t)rr * N + c);
                        v0 += rv.x; v1 += rv.y;
                    }
                    float2 o; o.x = v0; o.y = v1;
                    *reinterpret_cast<float2*>(Cf + (size_t)rr * N + c) = o;
                }
            }
        }
    }
}

// ---------------------------------------------------------------------------
// Full-fp16 tensor-core causal flash attention, double-buffered K/V.
// R14 changes: __launch_bounds__(256,2) (regs<=128 -> 2 CTAs/SM) and
// REVERSED qt order (longest CTAs first -> no scheduling tail).
// ---------------------------------------------------------------------------
#define AQ_OFF 0
#define AK_OFF(buf) (16384 + (buf) * 8192)
#define AV_OFF(buf) (32768 + (buf) * 8192)
#define AP_OFF 49152
#define ATTH_SMEM 65536

__device__ __forceinline__ void att_kv_load(
    uint32_t sb, int buf,
    const __half* __restrict__ kb, const __half* __restrict__ vb,
    int kt, int tid)
{
    const size_t rstr = 3 * DMODEL;
#pragma unroll
    for (int i = 0; i < 2; i++) {
        const int L = tid + i * 256;   // 0..511
        const int row = L >> 3, unit = L & 7;
        const size_t src = (size_t)(kt * 64 + row) * rstr + unit * 8;
        const uint32_t sw = SMEM_SWIZZLE_128B((uint32_t)(row * 128 + unit * 16));
        asm volatile("cp.async.cg.shared.global [%0], [%1], 16;"
                     :: "r"(sb + AK_OFF(buf) + sw), "l"(kb + src));
        asm volatile("cp.async.cg.shared.global [%0], [%1], 16;"
                     :: "r"(sb + AV_OFF(buf) + sw), "l"(vb + src));
    }
    asm volatile("cp.async.commit_group;");
}

__global__ __launch_bounds__(256, 2) void attn_h_kernel(
    const __half* __restrict__ qkv,
    __half* __restrict__ y)
{
    extern __shared__ char smc[];
    const uint32_t sb = smem_u32(smc);

    const int qt  = (SEQ / 128 - 1) - blockIdx.x;   // longest-first
    const int bh  = blockIdx.y;
    const int b   = bh >> 4;
    const int h   = bh & 15;
    const int tid = threadIdx.x;
    const int lane = tid & 31;
    const int wid  = tid >> 5;

    const size_t rstr = 3 * DMODEL;   // halves
    const __half* qb = qkv + ((size_t)b * SEQ + qt * 128) * rstr + h * HDIM;
    const __half* kb = qkv + (size_t)b * SEQ * rstr + DMODEL     + h * HDIM;
    const __half* vb = qkv + (size_t)b * SEQ * rstr + 2 * DMODEL + h * HDIM;

    // preload K/V tile 0 (overlaps with the Q load below)
    att_kv_load(sb, 0, kb, vb, 0, tid);

    // load Q tile, scaled by 1/sqrt(64) = 0.125 (exact in fp16)
    const __half2 qsc = __float2half2_rn(0.125f);
#pragma unroll
    for (int i = 0; i < 4; i++) {
        const int L = tid + i * 256;       // 0..1023
        const int row = L >> 3, unit = L & 7;
        uint4 t = *reinterpret_cast<const uint4*>(qb + (size_t)row * rstr + unit * 8);
        __half2* tp = reinterpret_cast<__half2*>(&t);
#pragma unroll
        for (int j = 0; j < 4; j++) tp[j] = __hmul2(tp[j], qsc);
        *reinterpret_cast<uint4*>(smc + AQ_OFF +
            SMEM_SWIZZLE_128B((uint32_t)(row * 128 + unit * 16))) = t;
    }

    float m0 = -1e30f, m1 = -1e30f, l0 = 0.f, l1 = 0.f;
    float acc[8][4];
#pragma unroll
    for (int nf = 0; nf < 8; nf++)
#pragma unroll
        for (int q = 0; q < 4; q++) acc[nf][q] = 0.f;

    const int lr  = lane & 7;
    const int lm8 = ((lane >> 3) & 1) * 8;
    const int ub  = lane >> 4;
    const int q0w = qt * 128 + wid * 16;
    const int nkv = 2 * qt + 2;

    for (int kt = 0; kt < nkv; kt++) {
        asm volatile("cp.async.wait_group 0;");   // K/V tile kt arrived
        __syncthreads();                          // all warps past compute(kt-1)
        if (kt + 1 < nkv)
            att_kv_load(sb, (kt + 1) & 1, kb, vb, kt + 1, tid);

        const uint32_t kT = sb + AK_OFF(kt & 1);
        const uint32_t vT = sb + AV_OFF(kt & 1);

        if (kt * 64 <= q0w + 15) {   // warp not fully masked
            // ---- S = Q @ K^T (warp tile 16 x 64) ----
            float s[8][4];
#pragma unroll
            for (int nf = 0; nf < 8; nf++)
#pragma unroll
                for (int q = 0; q < 4; q++) s[nf][q] = 0.f;

#pragma unroll
            for (int ks = 0; ks < 4; ks++) {
                const int u = ks * 2 + ub;
                unsigned a0, a1, a2, a3;
                ldsm4(a0, a1, a2, a3, sb + AQ_OFF + SMEM_SWIZZLE_128B(
                    (uint32_t)((wid * 16 + lr + lm8) * 128 + u * 16)));
#pragma unroll
                for (int nt = 0; nt < 4; nt++) {
                    unsigned b0, b1, b2, b3;
                    ldsm4(b0, b1, b2, b3, kT + SMEM_SWIZZLE_128B(
                        (uint32_t)((nt * 16 + lr + lm8) * 128 + u * 16)));
                    mma_f16(s[nt * 2 + 0], a0, a1, a2, a3, b0, b2);
                    mma_f16(s[nt * 2 + 1], a0, a1, a2, a3, b1, b3);
                }
            }

            // ---- causal mask (diagonal tiles only) ----
            if (kt >= 2 * qt) {
                const int r_lo = q0w + (lane >> 2);
#pragma unroll
                for (int nf = 0; nf < 8; nf++) {
                    int kg = kt * 64 + nf * 8 + 2 * (lane & 3);
                    if (kg     > r_lo)     s[nf][0] = -1e30f;
                    if (kg + 1 > r_lo)     s[nf][1] = -1e30f;
                    if (kg     > r_lo + 8) s[nf][2] = -1e30f;
                    if (kg + 1 > r_lo + 8) s[nf][3] = -1e30f;
                }
            }

            // ---- online softmax (rows lane>>2 and +8; quad shfl reduce) ----
            float mx0 = -1e30f, mx1 = -1e30f;
#pragma unroll
            for (int nf = 0; nf < 8; nf++) {
                mx0 = fmaxf(mx0, fmaxf(s[nf][0], s[nf][1]));
                mx1 = fmaxf(mx1, fmaxf(s[nf][2], s[nf][3]));
            }
            mx0 = fmaxf(mx0, __shfl_xor_sync(0xffffffffu, mx0, 1));
            mx0 = fmaxf(mx0, __shfl_xor_sync(0xffffffffu, mx0, 2));
            mx1 = fmaxf(mx1, __shfl_xor_sync(0xffffffffu, mx1, 1));
            mx1 = fmaxf(mx1, __shfl_xor_sync(0xffffffffu, mx1, 2));

            const float mn0 = fmaxf(m0, mx0);
            const float mn1 = fmaxf(m1, mx1);
            const float cor0 = __expf(m0 - mn0);
            const float cor1 = __expf(m1 - mn1);
            float sum0 = 0.f, sum1 = 0.f;
            const uint32_t pr0 = (uint32_t)((wid * 16 + (lane >> 2)) * 128
                                            + (lane & 3) * 4);
#pragma unroll
            for (int nf = 0; nf < 8; nf++) {
                float p0 = __expf(s[nf][0] - mn0);
                float p1 = __expf(s[nf][1] - mn0);
                float p2 = __expf(s[nf][2] - mn1);
                float p3 = __expf(s[nf][3] - mn1);
                sum0 += p0 + p1;
                sum1 += p2 + p3;
                *reinterpret_cast<__half2*>(smc + AP_OFF +
                    SMEM_SWIZZLE_128B(pr0 + (uint32_t)(nf * 16))) =
                    __floats2half2_rn(p0, p1);
                *reinterpret_cast<__half2*>(smc + AP_OFF +
                    SMEM_SWIZZLE_128B(pr0 + 8 * 128 + (uint32_t)(nf * 16))) =
                    __floats2half2_rn(p2, p3);
            }
            sum0 += __shfl_xor_sync(0xffffffffu, sum0, 1);
            sum0 += __shfl_xor_sync(0xffffffffu, sum0, 2);
            sum1 += __shfl_xor_sync(0xffffffffu, sum1, 1);
            sum1 += __shfl_xor_sync(0xffffffffu, sum1, 2);

            l0 = l0 * cor0 + sum0;
            l1 = l1 * cor1 + sum1;
            m0 = mn0; m1 = mn1;
#pragma unroll
            for (int nf = 0; nf < 8; nf++) {
                acc[nf][0] *= cor0; acc[nf][1] *= cor0;
                acc[nf][2] *= cor1; acc[nf][3] *= cor1;
            }
            __syncwarp();   // Ps visible to ldmatrix across lanes

            // ---- O += P @ V  (V via ldmatrix.trans) ----
#pragma unroll
            for (int ks = 0; ks < 4; ks++) {
                unsigned p0, p1, p2, p3;
                ldsm4(p0, p1, p2, p3, sb + AP_OFF + SMEM_SWIZZLE_128B(
                    (uint32_t)((wid * 16 + lr + lm8) * 128
                               + (ks * 2 + ub) * 16)));
#pragma unroll
                for (int nt = 0; nt < 4; nt++) {
                    unsigned v0, v1, v2, v3;
                    ldsm4_t(v0, v1, v2, v3, vT + SMEM_SWIZZLE_128B(
                        (uint32_t)((ks * 16 + lr + lm8) * 128
                                   + (nt * 2 + ub) * 16)));
                    mma_f16(acc[nt * 2 + 0], p0, p1, p2, p3, v0, v1);
                    mma_f16(acc[nt * 2 + 1], p0, p1, p2, p3, v2, v3);
                }
            }
            __syncwarp();   // PV reads done before next iter's Ps writes
        }
    }

    // ---- normalize + write fp16 ----
    const float inv0 = 1.0f / l0;
    const float inv1 = 1.0f / l1;
    const size_t row_lo = (size_t)b * SEQ + qt * 128 + wid * 16 + (lane >> 2);
#pragma unroll
    for (int nf = 0; nf < 8; nf++) {
        const int col = h * HDIM + nf * 8 + 2 * (lane & 3);
        *reinterpret_cast<__half2*>(&y[row_lo * DMODEL + col]) =
            __floats2half2_rn(acc[nf][0] * inv0, acc[nf][1] * inv0);
        *reinterpret_cast<__half2*>(&y[(row_lo + 8) * DMODEL + col]) =
            __floats2half2_rn(acc[nf][2] * inv1, acc[nf][3] * inv1);
    }
}

// ---------------------------------------------------------------------------
// Launch
// ---------------------------------------------------------------------------
extern "C" void kernel_launch(void* const* d_in, const int* in_sizes, int n_in,
                              void* d_out, int out_size)
{
    const float* x      = (const float*)d_in[0];
    const float* w_attn = (const float*)d_in[1];
    const float* w_o    = (const float*)d_in[2];
    const float* ln1_g  = (const float*)d_in[3];
    const float* ln1_b  = (const float*)d_in[4];
    const float* ln2_g  = (const float*)d_in[5];
    const float* ln2_b  = (const float*)d_in[6];
    const float* w_fc   = (const float*)d_in[7];
    const float* b_fc   = (const float*)d_in[8];
    const float* w_proj = (const float*)d_in[9];
    const float* b_proj = (const float*)d_in[10];
    float* out = (float*)d_out;

    __half *lnh, *qkvp, *yh, *hh, *wa, *wo, *wf, *wp;
    float *x1;
    cudaGetSymbolAddress((void**)&lnh,  g_lnh);
    cudaGetSymbolAddress((void**)&qkvp, g_qkv);
    cudaGetSymbolAddress((void**)&yh,   g_yh);
    cudaGetSymbolAddress((void**)&x1,   g_x1);
    cudaGetSymbolAddress((void**)&hh,   g_hh);
    cudaGetSymbolAddress((void**)&wa,   g_wa);
    cudaGetSymbolAddress((void**)&wo,   g_wo);
    cudaGetSymbolAddress((void**)&wf,   g_wf);
    cudaGetSymbolAddress((void**)&wp,   g_wp);

    cudaFuncSetAttribute(attn_h_kernel,
                         cudaFuncAttributeMaxDynamicSharedMemorySize, ATTH_SMEM);
    cudaFuncSetAttribute(h_gemm<1>,
                         cudaFuncAttributeMaxDynamicSharedMemorySize, HG_SMEM);
    cudaFuncSetAttribute(h_gemm<2>,
                         cudaFuncAttributeMaxDynamicSharedMemorySize, HG_SMEM);
    cudaFuncSetAttribute(h_gemm<3>,
                         cudaFuncAttributeMaxDynamicSharedMemorySize, HG_SMEM);
    cudaFuncSetAttribute(h_gemm<4>,
                         cudaFuncAttributeMaxDynamicSharedMemorySize, HG_SMEM);

    // 0) transpose + fp16-convert all weights (single launch)
    transpose_all_kernel<<<12288, 256>>>(
        w_attn, w_o, w_fc, w_proj, wa, wo, wf, wp);

    // 1) ln1 -> fp16
    ln_kernel<<<ROWS / 4, 256>>>(x, ln1_g, ln1_b, lnh);
    // 2) qkv = ln1 @ w_attn        [8192 x 3072] fp16 out
    h_gemm<4><<<dim3(3 * DMODEL / 128, ROWS / 128), 256, HG_SMEM>>>(
        ROWS, 3 * DMODEL, DMODEL, lnh, wa, nullptr, nullptr, qkvp);
    // 3) attention -> y (fp16, 2 CTAs/SM, longest-first)
    attn_h_kernel<<<dim3(SEQ / 128, BATCH * NHEAD), 256, ATTH_SMEM>>>(qkvp, yh);
    // 4) x1 = x + y @ w_o          fp32 out
    h_gemm<1><<<dim3(DMODEL / 128, ROWS / 128), 256, HG_SMEM>>>(
        ROWS, DMODEL, DMODEL, yh, wo, nullptr, x, x1);
    // 5) ln2 -> fp16
    ln_kernel<<<ROWS / 4, 256>>>(x1, ln2_g, ln2_b, lnh);
    // 6) h = gelu(ln2 @ w_fc + b_fc)   [8192 x 4096] fp16 out
    h_gemm<2><<<dim3(4 * DMODEL / 128, ROWS / 128), 256, HG_SMEM>>>(
        ROWS, 4 * DMODEL, DMODEL, lnh, wf, b_fc, nullptr, hh);
    // 7) out = x1 + h @ w_proj + b_proj   fp32 out
    h_gemm<3><<<dim3(DMODEL / 128, ROWS / 128), 256, HG_SMEM>>>(
        ROWS, DMODEL, 4 * DMODEL, hh, wp, b_proj, x1, out);
}

// round 17
// speedup vs baseline: 1.3559x; 1.0265x over previous
#include <cuda_runtime.h>
#include <cuda_fp16.h>
#include <math.h>
#include <stdint.h>

// ---------------------------------------------------------------------------
// Problem constants
// ---------------------------------------------------------------------------
#define BATCH 4
#define SEQ   2048
#define DMODEL 1024
#define NHEAD 16
#define HDIM  64
#define ROWS  (BATCH * SEQ)          // 8192
#define EPS   1e-5f

// ---------------------------------------------------------------------------
// Scratch buffers (static device globals: allocation-free per harness rules)
// ---------------------------------------------------------------------------
__device__ __half g_lnh[ROWS * DMODEL];       // 16 MB  LN output (fp16, GEMM A)
__device__ __half g_qkv[ROWS * 3 * DMODEL];   // 48 MB  qkv (fp16)
__device__ __half g_yh [ROWS * DMODEL];       // 16 MB  attention out (fp16)
__device__ float  g_x1 [ROWS * DMODEL];       // 32 MB  residual after attn
__device__ __half g_hh [ROWS * 4 * DMODEL];   // 64 MB  MLP hidden (fp16)
// fp16, TRANSPOSED weights [N][K]
__device__ __half g_wa [3 * DMODEL * DMODEL]; // 6 MB
__device__ __half g_wo [DMODEL * DMODEL];     // 2 MB
__device__ __half g_wf [4 * DMODEL * DMODEL]; // 8 MB
__device__ __half g_wp [DMODEL * 4 * DMODEL]; // 8 MB

// ---------------------------------------------------------------------------
// Helpers
// ---------------------------------------------------------------------------
__device__ __forceinline__ uint32_t smem_u32(const void* p) {
    uint32_t a;
    asm("{ .reg .u64 t; cvta.to.shared.u64 t, %1; cvt.u32.u64 %0, t; }"
        : "=r"(a) : "l"(p));
    return a;
}

#define SMEM_SWIZZLE_128B(off) ((off) ^ (((off) >> 3) & 0x70))

__device__ __forceinline__ void ldsm4(unsigned& r0, unsigned& r1,
                                      unsigned& r2, unsigned& r3, uint32_t a) {
    asm volatile("ldmatrix.sync.aligned.m8n8.x4.shared.b16 {%0,%1,%2,%3}, [%4];"
                 : "=r"(r0), "=r"(r1), "=r"(r2), "=r"(r3) : "r"(a));
}

__device__ __forceinline__ void ldsm4_t(unsigned& r0, unsigned& r1,
                                        unsigned& r2, unsigned& r3, uint32_t a) {
    asm volatile("ldmatrix.sync.aligned.m8n8.x4.trans.shared.b16 {%0,%1,%2,%3}, [%4];"
                 : "=r"(r0), "=r"(r1), "=r"(r2), "=r"(r3) : "r"(a));
}

__device__ __forceinline__ void mma_f16(float* c,
                                        unsigned a0, unsigned a1,
                                        unsigned a2, unsigned a3,
                                        unsigned b0, unsigned b1) {
    asm volatile(
        "mma.sync.aligned.m16n8k16.row.col.f32.f16.f16.f32 "
        "{%0,%1,%2,%3}, {%4,%5,%6,%7}, {%8,%9}, {%0,%1,%2,%3};"
        : "+f"(c[0]), "+f"(c[1]), "+f"(c[2]), "+f"(c[3])
        : "r"(a0), "r"(a1), "r"(a2), "r"(a3), "r"(b0), "r"(b1));
}

__device__ __forceinline__ float gelu_tanh(float x) {
    const float c0 = 0.7978845608028654f;  // sqrt(2/pi)
    const float c1 = 0.044715f;
    float t = tanhf(c0 * (x + c1 * x * x * x));
    return 0.5f * x * (1.0f + t);
}

// ---------------------------------------------------------------------------
// Merged transpose+fp16 for ALL FOUR weights in one launch.
// ---------------------------------------------------------------------------
__global__ __launch_bounds__(256) void transpose_all_kernel(
    const float* __restrict__ wa_in, const float* __restrict__ wo_in,
    const float* __restrict__ wf_in, const float* __restrict__ wp_in,
    __half* __restrict__ wa_out, __half* __restrict__ wo_out,
    __half* __restrict__ wf_out, __half* __restrict__ wp_out)
{
    __shared__ float t[32][33];
    const int tile = blockIdx.x;
    const float* in; __half* out; int K, N, local, tN;
    if (tile < 3072)      { in = wa_in; out = wa_out; K = 1024; N = 3072; local = tile;        tN = 96; }
    else if (tile < 4096) { in = wo_in; out = wo_out; K = 1024; N = 1024; local = tile - 3072; tN = 32; }
    else if (tile < 8192) { in = wf_in; out = wf_out; K = 1024; N = 4096; local = tile - 4096; tN = 128; }
    else                  { in = wp_in; out = wp_out; K = 4096; N = 1024; local = tile - 8192; tN = 32; }
    const int n0 = (local % tN) * 32;
    const int k0 = (local / tN) * 32;
    const int tx = threadIdx.x & 31;
    const int ty = threadIdx.x >> 5;   // 0..7

#pragma unroll
    for (int i = 0; i < 4; i++)
        t[ty + 8 * i][tx] = in[(size_t)(k0 + ty + 8 * i) * N + n0 + tx];
    __syncthreads();
#pragma unroll
    for (int i = 0; i < 4; i++)
        out[(size_t)(n0 + ty + 8 * i) * K + k0 + tx] =
            __float2half_rn(t[tx][ty + 8 * i]);
}

// ---------------------------------------------------------------------------
// LayerNorm: fp32 in, fp16 out. 4 rows per block (grid ROWS/4).
// ---------------------------------------------------------------------------
__global__ __launch_bounds__(256) void ln_kernel(
    const float* __restrict__ x,
    const float* __restrict__ g,
    const float* __restrict__ b,
    __half* __restrict__ out)
{
    const int tid = threadIdx.x;
    const int wid = tid >> 5, lane = tid & 31;
    const float4 gv = reinterpret_cast<const float4*>(g)[tid];
    const float4 bv = reinterpret_cast<const float4*>(b)[tid];
    __shared__ float red0[8], red1[8];

#pragma unroll
    for (int rr = 0; rr < 4; rr++) {
        const int row = blockIdx.x * 4 + rr;
        const float4 v = reinterpret_cast<const float4*>(
            x + (size_t)row * DMODEL)[tid];

        float s  = v.x + v.y + v.z + v.w;
        float ss = v.x*v.x + v.y*v.y + v.z*v.z + v.w*v.w;
#pragma unroll
        for (int o = 16; o > 0; o >>= 1) {
            s  += __shfl_xor_sync(0xffffffffu, s, o);
            ss += __shfl_xor_sync(0xffffffffu, ss, o);
        }
        if (lane == 0) { red0[wid] = s; red1[wid] = ss; }
        __syncthreads();
        float ts = 0.f, tss = 0.f;
#pragma unroll
        for (int w = 0; w < 8; w++) { ts += red0[w]; tss += red1[w]; }

        const float mean = ts * (1.0f / DMODEL);
        const float var  = tss * (1.0f / DMODEL) - mean * mean;
        const float rstd = rsqrtf(var + EPS);

        __half2 h0 = __floats2half2_rn((v.x - mean) * rstd * gv.x + bv.x,
                                       (v.y - mean) * rstd * gv.y + bv.y);
        __half2 h1 = __floats2half2_rn((v.z - mean) * rstd * gv.z + bv.z,
                                       (v.w - mean) * rstd * gv.w + bv.w);
        __half2* op = reinterpret_cast<__half2*>(out + (size_t)row * DMODEL);
        op[tid * 2 + 0] = h0;
        op[tid * 2 + 1] = h1;
        __syncthreads();   // red[] reuse next row
    }
}

// ---------------------------------------------------------------------------
// FP16 tensor-core GEMM v3: CTA tile 128x128, BK=64, 3-stage, 2 CTAs/SM,
// *** 128 threads = 4 warps as 2x2 grid of 64x64 warp tiles ***
// (halves smem crossbar traffic per mma vs the 8-warp 64x32 version:
//  per chunk 32 ldsm4 / 128 mma per warp -> crossbar 512 cyc < mma 1024 cyc)
// EPI: 0 none(f32) | 1 +res(f32) | 2 gelu(acc+bias)->fp16 | 3 +bias+res(f32)
//      4 plain fp16 out
// ---------------------------------------------------------------------------
#define HG_TILE 16384                        // 128 rows x 128 bytes
#define HG_A_OFF(s) ((s) * 2 * HG_TILE)
#define HG_B_OFF(s) ((s) * 2 * HG_TILE + HG_TILE)
#define HG_SMEM (3 * 2 * HG_TILE)            // 98304 B

__device__ __forceinline__ void hg_load_chunk(
    uint32_t smem_base, int stage,
    const __half* __restrict__ Ag, const __half* __restrict__ Bg,
    int K, int c, int tid)
{
    const int kk = c * 64;
#pragma unroll
    for (int i = 0; i < 8; i++) {
        const int L = tid + i * 128;          // 0..1023
        const int row = L >> 3;
        const int unit = L & 7;
        const uint32_t sw = SMEM_SWIZZLE_128B((uint32_t)(row * 128 + unit * 16));
        const __half* ap = Ag + (size_t)row * K + kk + unit * 8;
        const __half* bp = Bg + (size_t)row * K + kk + unit * 8;
        asm volatile("cp.async.cg.shared.global [%0], [%1], 16;"
                     :: "r"(smem_base + HG_A_OFF(stage) + sw), "l"(ap));
        asm volatile("cp.async.cg.shared.global [%0], [%1], 16;"
                     :: "r"(smem_base + HG_B_OFF(stage) + sw), "l"(bp));
    }
    asm volatile("cp.async.commit_group;");
}

template <int EPI>
__global__ __launch_bounds__(128, 2) void h_gemm(
    int M, int N, int K,
    const __half* __restrict__ A,
    const __half* __restrict__ Bt,
    const float* __restrict__ bias,
    const float* __restrict__ res,
    void* __restrict__ Cv)
{
    extern __shared__ char smem[];
    const uint32_t smem_base = smem_u32(smem);

    const int tid  = threadIdx.x;
    const int lane = tid & 31;
    const int wid  = tid >> 5;            // 0..3
    const int m_w  = (wid >> 1) * 64;     // warp M origin (0 or 64)
    const int n_w  = (wid & 1) * 64;      // warp N origin (0 or 64)

    const __half* Ag = A  + (size_t)(blockIdx.y * 128) * K;
    const __half* Bg = Bt + (size_t)(blockIdx.x * 128) * K;

    float acc[4][8][4];
#pragma unroll
    for (int i = 0; i < 4; i++)
#pragma unroll
        for (int j = 0; j < 8; j++)
#pragma unroll
            for (int q = 0; q < 4; q++) acc[i][j][q] = 0.f;

    const int lr  = lane & 7;
    const int lm8 = ((lane >> 3) & 1) * 8;
    const int ub  = lane >> 4;                 // 16B unit select (0/1)
    const int rowA = m_w + lr + lm8;           // + mf*16
    const int rowB = n_w + lr + lm8;           // + nt*16

    const int nk = K >> 6;

    hg_load_chunk(smem_base, 0, Ag, Bg, K, 0, tid);
    hg_load_chunk(smem_base, 1, Ag, Bg, K, 1, tid);

    int st = 0, ld = 2;
    for (int c = 0; c < nk; c++) {
        if (c + 1 < nk) {
            asm volatile("cp.async.wait_group 1;");
        } else {
            asm volatile("cp.async.wait_group 0;");
        }
        __syncthreads();
        if (c + 2 < nk) {
            hg_load_chunk(smem_base, ld, Ag, Bg, K, c + 2, tid);
        }

        const uint32_t aT = smem_base + HG_A_OFF(st);
        const uint32_t bT = smem_base + HG_B_OFF(st);

#pragma unroll
        for (int ks = 0; ks < 4; ks++) {
            const int u = ks * 2 + ub;
            unsigned av[4][4];
#pragma unroll
            for (int mf = 0; mf < 4; mf++) {
                const uint32_t off = (uint32_t)((rowA + mf * 16) * 128 + u * 16);
                ldsm4(av[mf][0], av[mf][1], av[mf][2], av[mf][3],
                      aT + SMEM_SWIZZLE_128B(off));
            }
            unsigned bv[4][4];
#pragma unroll
            for (int nt = 0; nt < 4; nt++) {
                const uint32_t off = (uint32_t)((rowB + nt * 16) * 128 + u * 16);
                ldsm4(bv[nt][0], bv[nt][1], bv[nt][2], bv[nt][3],
                      bT + SMEM_SWIZZLE_128B(off));
            }
#pragma unroll
            for (int mf = 0; mf < 4; mf++)
#pragma unroll
                for (int nt = 0; nt < 4; nt++) {
                    mma_f16(acc[mf][nt * 2 + 0],
                            av[mf][0], av[mf][1], av[mf][2], av[mf][3],
                            bv[nt][0], bv[nt][2]);
                    mma_f16(acc[mf][nt * 2 + 1],
                            av[mf][0], av[mf][1], av[mf][2], av[mf][3],
                            bv[nt][1], bv[nt][3]);
                }
        }
        st++; if (st == 3) st = 0;
        ld++; if (ld == 3) ld = 0;
    }

    // ---------------- epilogue (no smem use -> no final barrier) ----------
    float*  Cf = (float*)Cv;
    __half* Ch = (__half*)Cv;
    const int row0 = blockIdx.y * 128 + m_w;
    const int col0 = blockIdx.x * 128 + n_w;

#pragma unroll
    for (int mf = 0; mf < 4; mf++) {
#pragma unroll
        for (int nf = 0; nf < 8; nf++) {
            const int r = row0 + mf * 16 + (lane >> 2);
            const int c = col0 + nf * 8 + (lane & 3) * 2;
            float b0 = 0.f, b1 = 0.f;
            if (EPI == 2 || EPI == 3) { b0 = bias[c]; b1 = bias[c + 1]; }
#pragma unroll
            for (int half = 0; half < 2; half++) {
                const int rr = r + half * 8;
                float v0 = acc[mf][nf][half * 2 + 0];
                float v1 = acc[mf][nf][half * 2 + 1];
                if (EPI == 2) {
                    v0 = gelu_tanh(v0 + b0);
                    v1 = gelu_tanh(v1 + b1);
                    *reinterpret_cast<__half2*>(Ch + (size_t)rr * N + c) =
                        __floats2half2_rn(v0, v1);
                } else if (EPI == 4) {
                    *reinterpret_cast<__half2*>(Ch + (size_t)rr * N + c) =
                        __floats2half2_rn(v0, v1);
                } else {
                    if (EPI == 3) { v0 += b0; v1 += b1; }
                    if (EPI == 1 || EPI == 3) {
                        const float2 rv = *reinterpret_cast<const float2*>(
                            res + (size_t)rr * N + c);
                        v0 += rv.x; v1 += rv.y;
                    }
                    float2 o; o.x = v0; o.y = v1;
                    *reinterpret_cast<float2*>(Cf + (size_t)rr * N + c) = o;
                }
            }
        }
    }
}

// ---------------------------------------------------------------------------
// Full-fp16 tensor-core causal flash attention (unchanged from R15 WIN:
// 2 CTAs/SM, longest-first, double-buffered K/V).
// ---------------------------------------------------------------------------
#define AQ_OFF 0
#define AK_OFF(buf) (16384 + (buf) * 8192)
#define AV_OFF(buf) (32768 + (buf) * 8192)
#define AP_OFF 49152
#define ATTH_SMEM 65536

__device__ __forceinline__ void att_kv_load(
    uint32_t sb, int buf,
    const __half* __restrict__ kb, const __half* __restrict__ vb,
    int kt, int tid)
{
    const size_t rstr = 3 * DMODEL;
#pragma unroll
    for (int i = 0; i < 2; i++) {
        const int L = tid + i * 256;   // 0..511
        const int row = L >> 3, unit = L & 7;
        const size_t src = (size_t)(kt * 64 + row) * rstr + unit * 8;
        const uint32_t sw = SMEM_SWIZZLE_128B((uint32_t)(row * 128 + unit * 16));
        asm volatile("cp.async.cg.shared.global [%0], [%1], 16;"
                     :: "r"(sb + AK_OFF(buf) + sw), "l"(kb + src));
        asm volatile("cp.async.cg.shared.global [%0], [%1], 16;"
                     :: "r"(sb + AV_OFF(buf) + sw), "l"(vb + src));
    }
    asm volatile("cp.async.commit_group;");
}

__global__ __launch_bounds__(256, 2) void attn_h_kernel(
    const __half* __restrict__ qkv,
    __half* __restrict__ y)
{
    extern __shared__ char smc[];
    const uint32_t sb = smem_u32(smc);

    const int qt  = (SEQ / 128 - 1) - blockIdx.x;   // longest-first
    const int bh  = blockIdx.y;
    const int b   = bh >> 4;
    const int h   = bh & 15;
    const int tid = threadIdx.x;
    const int lane = tid & 31;
    const int wid  = tid >> 5;

    const size_t rstr = 3 * DMODEL;   // halves
    const __half* qb = qkv + ((size_t)b * SEQ + qt * 128) * rstr + h * HDIM;
    const __half* kb = qkv + (size_t)b * SEQ * rstr + DMODEL     + h * HDIM;
    const __half* vb = qkv + (size_t)b * SEQ * rstr + 2 * DMODEL + h * HDIM;

    att_kv_load(sb, 0, kb, vb, 0, tid);

    const __half2 qsc = __float2half2_rn(0.125f);
#pragma unroll
    for (int i = 0; i < 4; i++) {
        const int L = tid + i * 256;       // 0..1023
        const int row = L >> 3, unit = L & 7;
        uint4 t = *reinterpret_cast<const uint4*>(qb + (size_t)row * rstr + unit * 8);
        __half2* tp = reinterpret_cast<__half2*>(&t);
#pragma unroll
        for (int j = 0; j < 4; j++) tp[j] = __hmul2(tp[j], qsc);
        *reinterpret_cast<uint4*>(smc + AQ_OFF +
            SMEM_SWIZZLE_128B((uint32_t)(row * 128 + unit * 16))) = t;
    }

    float m0 = -1e30f, m1 = -1e30f, l0 = 0.f, l1 = 0.f;
    float acc[8][4];
#pragma unroll
    for (int nf = 0; nf < 8; nf++)
#pragma unroll
        for (int q = 0; q < 4; q++) acc[nf][q] = 0.f;

    const int lr  = lane & 7;
    const int lm8 = ((lane >> 3) & 1) * 8;
    const int ub  = lane >> 4;
    const int q0w = qt * 128 + wid * 16;
    const int nkv = 2 * qt + 2;

    for (int kt = 0; kt < nkv; kt++) {
        asm volatile("cp.async.wait_group 0;");
        __syncthreads();
        if (kt + 1 < nkv)
            att_kv_load(sb, (kt + 1) & 1, kb, vb, kt + 1, tid);

        const uint32_t kT = sb + AK_OFF(kt & 1);
        const uint32_t vT = sb + AV_OFF(kt & 1);

        if (kt * 64 <= q0w + 15) {
            float s[8][4];
#pragma unroll
            for (int nf = 0; nf < 8; nf++)
#pragma unroll
                for (int q = 0; q < 4; q++) s[nf][q] = 0.f;

#pragma unroll
            for (int ks = 0; ks < 4; ks++) {
                const int u = ks * 2 + ub;
                unsigned a0, a1, a2, a3;
                ldsm4(a0, a1, a2, a3, sb + AQ_OFF + SMEM_SWIZZLE_128B(
                    (uint32_t)((wid * 16 + lr + lm8) * 128 + u * 16)));
#pragma unroll
                for (int nt = 0; nt < 4; nt++) {
                    unsigned b0, b1, b2, b3;
                    ldsm4(b0, b1, b2, b3, kT + SMEM_SWIZZLE_128B(
                        (uint32_t)((nt * 16 + lr + lm8) * 128 + u * 16)));
                    mma_f16(s[nt * 2 + 0], a0, a1, a2, a3, b0, b2);
                    mma_f16(s[nt * 2 + 1], a0, a1, a2, a3, b1, b3);
                }
            }

            if (kt >= 2 * qt) {
                const int r_lo = q0w + (lane >> 2);
#pragma unroll
                for (int nf = 0; nf < 8; nf++) {
                    int kg = kt * 64 + nf * 8 + 2 * (lane & 3);
                    if (kg     > r_lo)     s[nf][0] = -1e30f;
                    if (kg + 1 > r_lo)     s[nf][1] = -1e30f;
                    if (kg     > r_lo + 8) s[nf][2] = -1e30f;
                    if (kg + 1 > r_lo + 8) s[nf][3] = -1e30f;
                }
            }

            float mx0 = -1e30f, mx1 = -1e30f;
#pragma unroll
            for (int nf = 0; nf < 8; nf++) {
                mx0 = fmaxf(mx0, fmaxf(s[nf][0], s[nf][1]));
                mx1 = fmaxf(mx1, fmaxf(s[nf][2], s[nf][3]));
            }
            mx0 = fmaxf(mx0, __shfl_xor_sync(0xffffffffu, mx0, 1));
            mx0 = fmaxf(mx0, __shfl_xor_sync(0xffffffffu, mx0, 2));
            mx1 = fmaxf(mx1, __shfl_xor_sync(0xffffffffu, mx1, 1));
            mx1 = fmaxf(mx1, __shfl_xor_sync(0xffffffffu, mx1, 2));

            const float mn0 = fmaxf(m0, mx0);
            const float mn1 = fmaxf(m1, mx1);
            const float cor0 = __expf(m0 - mn0);
            const float cor1 = __expf(m1 - mn1);
            float sum0 = 0.f, sum1 = 0.f;
            const uint32_t pr0 = (uint32_t)((wid * 16 + (lane >> 2)) * 128
                                            + (lane & 3) * 4);
#pragma unroll
            for (int nf = 0; nf < 8; nf++) {
                float p0 = __expf(s[nf][0] - mn0);
                float p1 = __expf(s[nf][1] - mn0);
                float p2 = __expf(s[nf][2] - mn1);
                float p3 = __expf(s[nf][3] - mn1);
                sum0 += p0 + p1;
                sum1 += p2 + p3;
                *reinterpret_cast<__half2*>(smc + AP_OFF +
                    SMEM_SWIZZLE_128B(pr0 + (uint32_t)(nf * 16))) =
                    __floats2half2_rn(p0, p1);
                *reinterpret_cast<__half2*>(smc + AP_OFF +
                    SMEM_SWIZZLE_128B(pr0 + 8 * 128 + (uint32_t)(nf * 16))) =
                    __floats2half2_rn(p2, p3);
            }
            sum0 += __shfl_xor_sync(0xffffffffu, sum0, 1);
            sum0 += __shfl_xor_sync(0xffffffffu, sum0, 2);
            sum1 += __shfl_xor_sync(0xffffffffu, sum1, 1);
            sum1 += __shfl_xor_sync(0xffffffffu, sum1, 2);

            l0 = l0 * cor0 + sum0;
            l1 = l1 * cor1 + sum1;
            m0 = mn0; m1 = mn1;
#pragma unroll
            for (int nf = 0; nf < 8; nf++) {
                acc[nf][0] *= cor0; acc[nf][1] *= cor0;
                acc[nf][2] *= cor1; acc[nf][3] *= cor1;
            }
            __syncwarp();

#pragma unroll
            for (int ks = 0; ks < 4; ks++) {
                unsigned p0, p1, p2, p3;
                ldsm4(p0, p1, p2, p3, sb + AP_OFF + SMEM_SWIZZLE_128B(
                    (uint32_t)((wid * 16 + lr + lm8) * 128
                               + (ks * 2 + ub) * 16)));
#pragma unroll
                for (int nt = 0; nt < 4; nt++) {
                    unsigned v0, v1, v2, v3;
                    ldsm4_t(v0, v1, v2, v3, vT + SMEM_SWIZZLE_128B(
                        (uint32_t)((ks * 16 + lr + lm8) * 128
                                   + (nt * 2 + ub) * 16)));
                    mma_f16(acc[nt * 2 + 0], p0, p1, p2, p3, v0, v1);
                    mma_f16(acc[nt * 2 + 1], p0, p1, p2, p3, v2, v3);
                }
            }
            __syncwarp();
        }
    }

    const float inv0 = 1.0f / l0;
    const float inv1 = 1.0f / l1;
    const size_t row_lo = (size_t)b * SEQ + qt * 128 + wid * 16 + (lane >> 2);
#pragma unroll
    for (int nf = 0; nf < 8; nf++) {
        const int col = h * HDIM + nf * 8 + 2 * (lane & 3);
        *reinterpret_cast<__half2*>(&y[row_lo * DMODEL + col]) =
            __floats2half2_rn(acc[nf][0] * inv0, acc[nf][1] * inv0);
        *reinterpret_cast<__half2*>(&y[(row_lo + 8) * DMODEL + col]) =
            __floats2half2_rn(acc[nf][2] * inv1, acc[nf][3] * inv1);
    }
}

// ---------------------------------------------------------------------------
// Launch
// ---------------------------------------------------------------------------
extern "C" void kernel_launch(void* const* d_in, const int* in_sizes, int n_in,
                              void* d_out, int out_size)
{
    const float* x      = (const float*)d_in[0];
    const float* w_attn = (const float*)d_in[1];
    const float* w_o    = (const float*)d_in[2];
    const float* ln1_g  = (const float*)d_in[3];
    const float* ln1_b  = (const float*)d_in[4];
    const float* ln2_g  = (const float*)d_in[5];
    const float* ln2_b  = (const float*)d_in[6];
    const float* w_fc   = (const float*)d_in[7];
    const float* b_fc   = (const float*)d_in[8];
    const float* w_proj = (const float*)d_in[9];
    const float* b_proj = (const float*)d_in[10];
    float* out = (float*)d_out;

    __half *lnh, *qkvp, *yh, *hh, *wa, *wo, *wf, *wp;
    float *x1;
    cudaGetSymbolAddress((void**)&lnh,  g_lnh);
    cudaGetSymbolAddress((void**)&qkvp, g_qkv);
    cudaGetSymbolAddress((void**)&yh,   g_yh);
    cudaGetSymbolAddress((void**)&x1,   g_x1);
    cudaGetSymbolAddress((void**)&hh,   g_hh);
    cudaGetSymbolAddress((void**)&wa,   g_wa);
    cudaGetSymbolAddress((void**)&wo,   g_wo);
    cudaGetSymbolAddress((void**)&wf,   g_wf);
    cudaGetSymbolAddress((void**)&wp,   g_wp);

    cudaFuncSetAttribute(attn_h_kernel,
                         cudaFuncAttributeMaxDynamicSharedMemorySize, ATTH_SMEM);
    cudaFuncSetAttribute(h_gemm<1>,
                         cudaFuncAttributeMaxDynamicSharedMemorySize, HG_SMEM);
    cudaFuncSetAttribute(h_gemm<2>,
                         cudaFuncAttributeMaxDynamicSharedMemorySize, HG_SMEM);
    cudaFuncSetAttribute(h_gemm<3>,
                         cudaFuncAttributeMaxDynamicSharedMemorySize, HG_SMEM);
    cudaFuncSetAttribute(h_gemm<4>,
                         cudaFuncAttributeMaxDynamicSharedMemorySize, HG_SMEM);

    // 0) transpose + fp16-convert all weights (single launch)
    transpose_all_kernel<<<12288, 256>>>(
        w_attn, w_o, w_fc, w_proj, wa, wo, wf, wp);

    // 1) ln1 -> fp16
    ln_kernel<<<ROWS / 4, 256>>>(x, ln1_g, ln1_b, lnh);
    // 2) qkv = ln1 @ w_attn        [8192 x 3072] fp16 out
    h_gemm<4><<<dim3(3 * DMODEL / 128, ROWS / 128), 128, HG_SMEM>>>(
        ROWS, 3 * DMODEL, DMODEL, lnh, wa, nullptr, nullptr, qkvp);
    // 3) attention -> y (fp16)
    attn_h_kernel<<<dim3(SEQ / 128, BATCH * NHEAD), 256, ATTH_SMEM>>>(qkvp, yh);
    // 4) x1 = x + y @ w_o          fp32 out
    h_gemm<1><<<dim3(DMODEL / 128, ROWS / 128), 128, HG_SMEM>>>(
        ROWS, DMODEL, DMODEL, yh, wo, nullptr, x, x1);
    // 5) ln2 -> fp16
    ln_kernel<<<ROWS / 4, 256>>>(x1, ln2_g, ln2_b, lnh);
    // 6) h = gelu(ln2 @ w_fc + b_fc)   [8192 x 4096] fp16 out
    h_gemm<2><<<dim3(4 * DMODEL / 128, ROWS / 128), 128, HG_SMEM>>>(
        ROWS, 4 * DMODEL, DMODEL, lnh, wf, b_fc, nullptr, hh);
    // 7) out = x1 + h @ w_proj + b_proj   fp32 out
    h_gemm<3><<<dim3(DMODEL / 128, ROWS / 128), 128, HG_SMEM>>>(
        ROWS, DMODEL, 4 * DMODEL, hh, wp, b_proj, x1, out);
}